// round 11
// baseline (speedup 1.0000x reference)
#include <cuda_runtime.h>
#include <cuda_bf16.h>
#include <mma.h>
#include <math.h>
#include <stdint.h>

using namespace nvcuda;

#define NN 50000
#define EE 800000
#define BN_EPS 1e-5f

// ---------------- scratch (static device globals; no runtime alloc) ----------------
__device__ float g_h[NN * 256];
__device__ float g_agg[NN * 256];
__device__ float g_s1[NN * 64];
__device__ float g_s2[NN * 64];
__device__ float g_als[NN * 4];
__device__ float g_ald[NN * 4];
__device__ int   g_cnt[NN];
__device__ int   g_rs[NN + 1];
__device__ int   g_cur[NN];
__device__ int   g_srcs[EE];
__device__ float g_stats[2048];      // 4 regions of 512
__device__ float g_scale[256];
__device__ float g_shift[256];
__device__ __nv_bfloat16 g_ahi[NN * 256];
__device__ __nv_bfloat16 g_alo[NN * 256];
__device__ __nv_bfloat16 g_wthi[256 * 256];
__device__ __nv_bfloat16 g_wtlo[256 * 256];

// ---------------- tiny utility kernels ----------------
__global__ void k_zeroi(int* __restrict__ p, int n) {
    int i = blockIdx.x * blockDim.x + threadIdx.x;
    if (i < n) p[i] = 0;
}
__global__ void k_zerof(float* __restrict__ p, int n) {
    int i = blockIdx.x * blockDim.x + threadIdx.x;
    if (i < n) p[i] = 0.f;
}

// ---------------- fp32 -> bf16 hi/lo split conversions ----------------
__global__ void k_cvt(const float* __restrict__ a, __nv_bfloat16* __restrict__ hi,
                      __nv_bfloat16* __restrict__ lo, int total) {
    int i = blockIdx.x * blockDim.x + threadIdx.x;
    if (i >= total) return;
    float v = a[i];
    __nv_bfloat16 h = __float2bfloat16(v);
    hi[i] = h;
    lo[i] = __float2bfloat16(v - __bfloat162float(h));
}

__global__ void k_cvt_bn(const float* __restrict__ a, const float* __restrict__ sc,
                         const float* __restrict__ sh, __nv_bfloat16* __restrict__ hi,
                         __nv_bfloat16* __restrict__ lo, int total) {
    int i = blockIdx.x * blockDim.x + threadIdx.x;
    if (i >= total) return;
    int c = i & 255;
    float v = fmaxf(fmaf(a[i], sc[c], sh[c]), 0.f);
    __nv_bfloat16 h = __float2bfloat16(v);
    hi[i] = h;
    lo[i] = __float2bfloat16(v - __bfloat162float(h));
}

// W [K,cout] -> transposed Wt [cout,K] hi/lo bf16
__global__ void k_cvt_wt(const float* __restrict__ w, __nv_bfloat16* __restrict__ hi,
                         __nv_bfloat16* __restrict__ lo, int K, int cout) {
    int i = blockIdx.x * blockDim.x + threadIdx.x;
    if (i >= K * cout) return;
    int k = i / cout;
    int c = i - k * cout;
    float v = w[i];
    __nv_bfloat16 h = __float2bfloat16(v);
    hi[c * K + k] = h;
    lo[c * K + k] = __float2bfloat16(v - __bfloat162float(h));
}

// ---------------- CSR build ----------------
__global__ void k_count(const int* __restrict__ ei, int* __restrict__ cnt) {
    int e = blockIdx.x * blockDim.x + threadIdx.x;
    if (e < EE) atomicAdd(&cnt[ei[EE + e]], 1);
}

// scan also initializes cur (= rs)
__global__ void k_scan(const int* __restrict__ cnt, int* __restrict__ rs,
                       int* __restrict__ cur) {
    __shared__ int sh[1024];
    int t = threadIdx.x;
    const int n = NN;
    int chunk = (n + 1023) >> 10;
    int b0 = t * chunk;
    int b1 = b0 + chunk; if (b1 > n) b1 = n; if (b0 > n) b0 = n;
    int local = 0;
    for (int i = b0; i < b1; i++) local += cnt[i];
    sh[t] = local;
    __syncthreads();
    for (int off = 1; off < 1024; off <<= 1) {
        int v = (t >= off) ? sh[t - off] : 0;
        __syncthreads();
        sh[t] += v;
        __syncthreads();
    }
    int base = sh[t] - local;
    for (int i = b0; i < b1; i++) { rs[i] = base; cur[i] = base; base += cnt[i]; }
    if (t == 1023) rs[n] = sh[1023];
}

__global__ void k_scatter(const int* __restrict__ ei, int* __restrict__ cur,
                          int* __restrict__ srcs) {
    int e = blockIdx.x * blockDim.x + threadIdx.x;
    if (e < EE) {
        int d = ei[EE + e];
        int pos = atomicAdd(&cur[d], 1);
        srcs[pos] = ei[e];
    }
}

// ================= WMMA bf16-split GEMM, cp.async double-buffered =================
#define WG_LD        40
#define WG_MAT       (128 * WG_LD)
#define WG_BUF       (4 * WG_MAT)
#define WG_BUF_BYTES (WG_BUF * 2)
#define WG_SMEM      (2 * WG_BUF_BYTES)

__device__ __forceinline__ void cp16(uint32_t dst, const void* src, int sz) {
    asm volatile("cp.async.ca.shared.global [%0], [%1], 16, %2;"
                 :: "r"(dst), "l"(src), "r"(sz));
}
__device__ __forceinline__ void cp_commit() {
    asm volatile("cp.async.commit_group;" ::: "memory");
}
template <int N>
__device__ __forceinline__ void cp_wait() {
    asm volatile("cp.async.wait_group %0;" :: "n"(N) : "memory");
}

__global__ void __launch_bounds__(256, 2)
k_wgemm(const __nv_bfloat16* __restrict__ Ahi, const __nv_bfloat16* __restrict__ Alo,
        const __nv_bfloat16* __restrict__ Bhi, const __nv_bfloat16* __restrict__ Blo,
        float* __restrict__ C, const float* __restrict__ asrc,
        const float* __restrict__ adst, float* __restrict__ als,
        float* __restrict__ ald, int n, int K, int cout) {
    extern __shared__ __align__(16) __nv_bfloat16 sm[];
    int tid = threadIdx.x;
    int wid = tid >> 5;
    int lane = tid & 31;
    int wm = wid >> 1;
    int wn = wid & 1;
    int row0 = blockIdx.y * 128;
    int col0 = blockIdx.x * 128;

    int r0i = tid >> 2,         c0i = (tid & 3) * 8;
    int r1i = (tid + 256) >> 2, c1i = (tid & 3) * 8;
    int gr0 = row0 + r0i, gr1 = row0 + r1i;
    int sza0 = (gr0 < n) ? 16 : 0;
    int sza1 = (gr1 < n) ? 16 : 0;
    int ar0 = (gr0 < n) ? gr0 : 0;
    int ar1 = (gr1 < n) ? gr1 : 0;

    uint32_t sbase = (uint32_t)__cvta_generic_to_shared(sm);
    uint32_t so0 = (uint32_t)((r0i * WG_LD + c0i) * 2);
    uint32_t so1 = (uint32_t)((r1i * WG_LD + c1i) * 2);
    const uint32_t MATB = WG_MAT * 2;

    int nch = K >> 5;

    auto issue = [&](int ch, int buf) {
        int k0 = ch << 5;
        uint32_t b = sbase + (uint32_t)buf * WG_BUF_BYTES;
        size_t a0 = (size_t)ar0 * K + k0 + c0i;
        size_t a1 = (size_t)ar1 * K + k0 + c1i;
        size_t b0 = (size_t)(col0 + r0i) * K + k0 + c0i;
        size_t b1 = (size_t)(col0 + r1i) * K + k0 + c1i;
        cp16(b + so0, &Ahi[a0], sza0);
        cp16(b + so1, &Ahi[a1], sza1);
        cp16(b + MATB + so0, &Alo[a0], sza0);
        cp16(b + MATB + so1, &Alo[a1], sza1);
        cp16(b + 2 * MATB + so0, &Bhi[b0], 16);
        cp16(b + 2 * MATB + so1, &Bhi[b1], 16);
        cp16(b + 3 * MATB + so0, &Blo[b0], 16);
        cp16(b + 3 * MATB + so1, &Blo[b1], 16);
    };

    issue(0, 0);
    cp_commit();

    wmma::fragment<wmma::accumulator, 16, 16, 16, float> acc[2][4];
#pragma unroll
    for (int i = 0; i < 2; i++)
#pragma unroll
        for (int j = 0; j < 4; j++) wmma::fill_fragment(acc[i][j], 0.f);

    for (int ch = 0; ch < nch; ch++) {
        if (ch + 1 < nch) {
            issue(ch + 1, (ch + 1) & 1);
            cp_commit();
            cp_wait<1>();
        } else {
            cp_wait<0>();
        }
        __syncthreads();
        int cur = (ch & 1) * WG_BUF;
#pragma unroll
        for (int ks = 0; ks < 2; ks++) {
            wmma::fragment<wmma::matrix_a, 16, 16, 16, __nv_bfloat16, wmma::row_major> ah[2], al[2];
            const __nv_bfloat16* pa = &sm[cur + (wm * 32) * WG_LD + ks * 16];
            wmma::load_matrix_sync(ah[0], pa, WG_LD);
            wmma::load_matrix_sync(ah[1], pa + 16 * WG_LD, WG_LD);
            wmma::load_matrix_sync(al[0], pa + WG_MAT, WG_LD);
            wmma::load_matrix_sync(al[1], pa + WG_MAT + 16 * WG_LD, WG_LD);
#pragma unroll
            for (int j = 0; j < 4; j++) {
                wmma::fragment<wmma::matrix_b, 16, 16, 16, __nv_bfloat16, wmma::col_major> bh, bl;
                const __nv_bfloat16* pb =
                    &sm[cur + 2 * WG_MAT + (wn * 64 + j * 16) * WG_LD + ks * 16];
                wmma::load_matrix_sync(bh, pb, WG_LD);
                wmma::load_matrix_sync(bl, pb + WG_MAT, WG_LD);
                wmma::mma_sync(acc[0][j], ah[0], bh, acc[0][j]);
                wmma::mma_sync(acc[0][j], ah[0], bl, acc[0][j]);
                wmma::mma_sync(acc[0][j], al[0], bh, acc[0][j]);
                wmma::mma_sync(acc[1][j], ah[1], bh, acc[1][j]);
                wmma::mma_sync(acc[1][j], ah[1], bl, acc[1][j]);
                wmma::mma_sync(acc[1][j], al[1], bh, acc[1][j]);
            }
        }
        __syncthreads();
    }

    // ---- epilogue: stage C tile in smem, write C coalesced, compute als/ald ----
    float* smC = reinterpret_cast<float*>(sm);
    const int CLD = 132;
#pragma unroll
    for (int i = 0; i < 2; i++)
#pragma unroll
        for (int j = 0; j < 4; j++)
            wmma::store_matrix_sync(smC + (wm * 32 + i * 16) * CLD + wn * 64 + j * 16,
                                    acc[i][j], CLD, wmma::mem_row_major);
    __syncthreads();

    for (int t = tid; t < 128 * 32; t += 256) {
        int r = t >> 5, c4 = (t & 31) * 4;
        int gr = row0 + r;
        if (gr < n)
            *reinterpret_cast<float4*>(&C[(size_t)gr * cout + col0 + c4]) =
                *reinterpret_cast<const float4*>(&smC[r * CLD + c4]);
    }

    int half = lane >> 4;
    int l16 = lane & 15;
    int head = blockIdx.x * 2 + half;
    float4 as4 = *reinterpret_cast<const float4*>(&asrc[head * 64 + l16 * 4]);
    float4 ad4 = *reinterpret_cast<const float4*>(&adst[head * 64 + l16 * 4]);
#pragma unroll
    for (int rr = 0; rr < 16; rr++) {
        int r = wid * 16 + rr;
        int gr = row0 + r;
        float4 v = *reinterpret_cast<const float4*>(&smC[r * CLD + half * 64 + l16 * 4]);
        float vs = v.x * as4.x + v.y * as4.y + v.z * as4.z + v.w * as4.w;
        float vd = v.x * ad4.x + v.y * ad4.y + v.z * ad4.z + v.w * ad4.w;
#pragma unroll
        for (int o = 8; o; o >>= 1) {
            vs += __shfl_xor_sync(0xffffffffu, vs, o);
            vd += __shfl_xor_sync(0xffffffffu, vd, o);
        }
        if (l16 == 0 && gr < n) {
            als[gr * 4 + head] = vs;
            ald[gr * 4 + head] = vd;
        }
    }
}

// ---------------- small GEMM (64-wide), fused bn prep (from stats) + relu on A ----
__global__ void k_gemm(const float* __restrict__ A, const float* __restrict__ W,
                       const float* __restrict__ bias, float* __restrict__ C,
                       int n, int K, int cout,
                       const float* __restrict__ stats, const float* __restrict__ bng,
                       const float* __restrict__ bnb, int dorelu) {
    __shared__ __align__(16) float As[16][68];
    __shared__ __align__(16) float Ws[16][64];
    __shared__ float ssc[64], ssh[64];
    int tid = threadIdx.x;
    int tx = tid & 15;
    int ty = tid >> 4;
    int row0 = blockIdx.y * 64;
    int col0 = blockIdx.x * 64;

    if (stats && tid < 64) {
        float invn = 1.f / (float)n;
        float mu = stats[tid] * invn;
        float var = stats[64 + tid] * invn - mu * mu;
        float sc = rsqrtf(var + BN_EPS) * bng[tid];
        ssc[tid] = sc;
        ssh[tid] = bnb[tid] - mu * sc;
    }
    __syncthreads();

    float acc[4][4] = {};
    for (int k0 = 0; k0 < K; k0 += 16) {
#pragma unroll
        for (int i = 0; i < 4; i++) {
            int idx = tid + i * 256;
            int kk = idx & 15;
            int m  = idx >> 4;
            int gr = row0 + m;
            float v = (gr < n) ? A[(size_t)gr * K + k0 + kk] : 0.f;
            if (stats) {
                v = fmaf(v, ssc[k0 + kk], ssh[k0 + kk]);
                if (dorelu) v = fmaxf(v, 0.f);
            }
            As[kk][m] = v;
        }
#pragma unroll
        for (int i = 0; i < 4; i++) {
            int idx = tid + i * 256;
            int col = idx & 63;
            int kk  = idx >> 6;
            Ws[kk][col] = W[(size_t)(k0 + kk) * cout + col0 + col];
        }
        __syncthreads();
#pragma unroll
        for (int kk = 0; kk < 16; kk++) {
            float4 ra = *reinterpret_cast<const float4*>(&As[kk][ty * 4]);
            float4 rb = *reinterpret_cast<const float4*>(&Ws[kk][tx * 4]);
            float a[4] = {ra.x, ra.y, ra.z, ra.w};
            float b[4] = {rb.x, rb.y, rb.z, rb.w};
#pragma unroll
            for (int i = 0; i < 4; i++)
#pragma unroll
                for (int j = 0; j < 4; j++)
                    acc[i][j] = fmaf(a[i], b[j], acc[i][j]);
        }
        __syncthreads();
    }
#pragma unroll
    for (int i = 0; i < 4; i++) {
        int gr = row0 + ty * 4 + i;
        if (gr >= n) continue;
#pragma unroll
        for (int j = 0; j < 4; j++) {
            int gc = col0 + tx * 4 + j;
            float v = acc[i][j];
            if (bias) v += bias[gc];
            C[(size_t)gr * cout + gc] = v;
        }
    }
}

// ---------------- fused softmax + aggregation ----------------
// 4 nodes/block, 64 threads/node. Phase 1: p = exp(leaky(als[src]+ald)) for a
// <=64-edge chunk into smem (one edge/thread, all heads). Phase 2: aggregate,
// accumulating den per-thread for free. Divide at end.
template <bool MEAN>
__global__ void k_aggf(const float* __restrict__ hbuf, const float* __restrict__ als,
                       const float* __restrict__ ald, const int* __restrict__ rs,
                       const int* __restrict__ srcs, const float* __restrict__ bias,
                       float* __restrict__ out) {
    __shared__ float sp[4][64][4];
    __shared__ int   ssrc[4][64];
    __shared__ float smean[4][256];
    __shared__ int   snch;
    int tid = threadIdx.x;
    int grp = tid >> 6;
    int lt  = tid & 63;
    int node = blockIdx.x * 4 + grp;

    int beg = 0, end = 0;
    if (node < NN) { beg = rs[node]; end = rs[node + 1]; }
    int deg = end - beg;

    if (tid == 0) snch = 0;
    __syncthreads();
    if (lt == 0) atomicMax(&snch, (deg + 63) >> 6);
    __syncthreads();
    int nch = snch;

    float4 ald4 = make_float4(0.f, 0.f, 0.f, 0.f);
    if (node < NN) ald4 = *reinterpret_cast<const float4*>(&ald[node * 4]);

    int h = lt >> 4;
    float4 acc = make_float4(0.f, 0.f, 0.f, 0.f);
    float dloc = 0.f;

    for (int ch = 0; ch < nch; ch++) {
        __syncthreads();    // protect smem reuse across chunks
        int j = beg + ch * 64 + lt;
        if (j < end) {
            int s = srcs[j];
            ssrc[grp][lt] = s;
            float4 a = *reinterpret_cast<const float4*>(&als[s * 4]);
            float e0 = a.x + ald4.x; e0 = e0 > 0.f ? e0 : 0.2f * e0;
            float e1 = a.y + ald4.y; e1 = e1 > 0.f ? e1 : 0.2f * e1;
            float e2 = a.z + ald4.z; e2 = e2 > 0.f ? e2 : 0.2f * e2;
            float e3 = a.w + ald4.w; e3 = e3 > 0.f ? e3 : 0.2f * e3;
            sp[grp][lt][0] = __expf(e0);
            sp[grp][lt][1] = __expf(e1);
            sp[grp][lt][2] = __expf(e2);
            sp[grp][lt][3] = __expf(e3);
        }
        __syncthreads();
        int cend = deg - ch * 64;
        if (cend > 64) cend = 64;
        int e = 0;
        for (; e + 1 < cend; e += 2) {
            int s0 = ssrc[grp][e], s1 = ssrc[grp][e + 1];
            float p0 = sp[grp][e][h], p1 = sp[grp][e + 1][h];
            float4 v0 = *reinterpret_cast<const float4*>(&hbuf[(size_t)s0 * 256 + lt * 4]);
            float4 v1 = *reinterpret_cast<const float4*>(&hbuf[(size_t)s1 * 256 + lt * 4]);
            acc.x = fmaf(v0.x, p0, fmaf(v1.x, p1, acc.x));
            acc.y = fmaf(v0.y, p0, fmaf(v1.y, p1, acc.y));
            acc.z = fmaf(v0.z, p0, fmaf(v1.z, p1, acc.z));
            acc.w = fmaf(v0.w, p0, fmaf(v1.w, p1, acc.w));
            dloc += p0 + p1;
        }
        if (e < cend) {
            int s0 = ssrc[grp][e];
            float p0 = sp[grp][e][h];
            float4 v0 = *reinterpret_cast<const float4*>(&hbuf[(size_t)s0 * 256 + lt * 4]);
            acc.x = fmaf(v0.x, p0, acc.x);
            acc.y = fmaf(v0.y, p0, acc.y);
            acc.z = fmaf(v0.z, p0, acc.z);
            acc.w = fmaf(v0.w, p0, acc.w);
            dloc += p0;
        }
    }

    float inv = 1.f / (dloc + 1e-16f);
    acc.x *= inv; acc.y *= inv; acc.z *= inv; acc.w *= inv;

    if (!MEAN) {
        if (node < NN) {
            float4 bb = *reinterpret_cast<const float4*>(&bias[lt * 4]);
            acc.x += bb.x; acc.y += bb.y; acc.z += bb.z; acc.w += bb.w;
            *reinterpret_cast<float4*>(&out[(size_t)node * 256 + lt * 4]) = acc;
        }
    } else {
        *reinterpret_cast<float4*>(&smean[grp][lt * 4]) = acc;
        __syncthreads();
        if (node < NN && lt < 16) {
            float4 o;
            float* row = smean[grp];
            int c = lt * 4;
            o.x = (row[c + 0] + row[c + 64] + row[c + 128] + row[c + 192]) * 0.25f + bias[c + 0];
            o.y = (row[c + 1] + row[c + 65] + row[c + 129] + row[c + 193]) * 0.25f + bias[c + 1];
            o.z = (row[c + 2] + row[c + 66] + row[c + 130] + row[c + 194]) * 0.25f + bias[c + 2];
            o.w = (row[c + 3] + row[c + 67] + row[c + 131] + row[c + 195]) * 0.25f + bias[c + 3];
            *reinterpret_cast<float4*>(&out[(size_t)node * 64 + c]) = o;
        }
    }
}

// ---------------- batchnorm stats / prep ----------------
__global__ void k_bnstats(const float* __restrict__ x, float* __restrict__ stats,
                          int n, int C, int rowsPerBlk) {
    int c = threadIdx.x % C;
    int rl = threadIdx.x / C;
    int lanes = blockDim.x / C;
    int r0 = blockIdx.x * rowsPerBlk;
    int r1 = r0 + rowsPerBlk; if (r1 > n) r1 = n;
    float s = 0.f, s2 = 0.f;
    for (int r = r0 + rl; r < r1; r += lanes) {
        float v = x[(size_t)r * C + c];
        s += v; s2 += v * v;
    }
    __shared__ float sh[2][256];
    sh[0][threadIdx.x] = s; sh[1][threadIdx.x] = s2;
    __syncthreads();
    if (rl == 0) {
        for (int l = 1; l < lanes; l++) {
            s += sh[0][c + l * C]; s2 += sh[1][c + l * C];
        }
        atomicAdd(&stats[c], s);
        atomicAdd(&stats[C + c], s2);
    }
}

__global__ void k_bnprep(const float* __restrict__ stats, const float* __restrict__ g,
                         const float* __restrict__ b, float* __restrict__ scale,
                         float* __restrict__ shift, int n, int C) {
    int c = threadIdx.x + blockIdx.x * blockDim.x;
    if (c >= C) return;
    float invn = 1.f / (float)n;
    float mu = stats[c] * invn;
    float var = stats[C + c] * invn - mu * mu;
    float sc = rsqrtf(var + BN_EPS) * g[c];
    scale[c] = sc;
    shift[c] = b[c] - mu * sc;
}

// ---------------- fused bn4 + relu + final dot + sigmoid ----------------
__global__ void k_bnfin(const float* __restrict__ x, const float* __restrict__ stats,
                        const float* __restrict__ g, const float* __restrict__ b,
                        const float* __restrict__ w, const float* __restrict__ fb,
                        float* __restrict__ out) {
    int row = blockIdx.x * 8 + (threadIdx.x >> 5);
    int lane = threadIdx.x & 31;
    if (row >= NN) return;
    float invn = 1.f / (float)NN;
    float s = 0.f;
#pragma unroll
    for (int half = 0; half < 2; half++) {
        int c = lane + half * 32;
        float mu = stats[c] * invn;
        float var = stats[64 + c] * invn - mu * mu;
        float v = (x[(size_t)row * 64 + c] - mu) * rsqrtf(var + BN_EPS) * g[c] + b[c];
        v = fmaxf(v, 0.f);
        s = fmaf(v, w[c], s);
    }
#pragma unroll
    for (int o = 16; o; o >>= 1) s += __shfl_xor_sync(0xffffffffu, s, o);
    if (lane == 0) out[row] = 1.f / (1.f + __expf(-(s + fb[0])));
}

// ---------------- host launch ----------------
extern "C" void kernel_launch(void* const* d_in, const int* in_sizes, int n_in,
                              void* d_out, int out_size) {
    const float* x        = (const float*)d_in[0];
    const int*   ei       = (const int*)d_in[1];
    const float* W1       = (const float*)d_in[2];
    const float* a1_src   = (const float*)d_in[3];
    const float* a1_dst   = (const float*)d_in[4];
    const float* b1       = (const float*)d_in[5];
    const float* W2       = (const float*)d_in[6];
    const float* a2_src   = (const float*)d_in[7];
    const float* a2_dst   = (const float*)d_in[8];
    const float* b2       = (const float*)d_in[9];
    const float* bn1_g    = (const float*)d_in[10];
    const float* bn1_b    = (const float*)d_in[11];
    const float* bn2_g    = (const float*)d_in[12];
    const float* bn2_b    = (const float*)d_in[13];
    const float* bn3_g    = (const float*)d_in[14];
    const float* bn3_b    = (const float*)d_in[15];
    const float* bn4_g    = (const float*)d_in[16];
    const float* bn4_b    = (const float*)d_in[17];
    const float* lin1_W   = (const float*)d_in[18];
    const float* lin1_b   = (const float*)d_in[19];
    const float* lin2_W   = (const float*)d_in[20];
    const float* lin2_b   = (const float*)d_in[21];
    const float* fin_W    = (const float*)d_in[22];
    const float* fin_b    = (const float*)d_in[23];
    float* out            = (float*)d_out;

    float *p_h, *p_agg, *p_s1, *p_s2, *p_als, *p_ald, *p_stats;
    float *p_scale, *p_shift;
    int *p_cnt, *p_rs, *p_cur, *p_srcs;
    __nv_bfloat16 *p_ahi, *p_alo, *p_wthi, *p_wtlo;
    cudaGetSymbolAddress((void**)&p_h, g_h);
    cudaGetSymbolAddress((void**)&p_agg, g_agg);
    cudaGetSymbolAddress((void**)&p_s1, g_s1);
    cudaGetSymbolAddress((void**)&p_s2, g_s2);
    cudaGetSymbolAddress((void**)&p_als, g_als);
    cudaGetSymbolAddress((void**)&p_ald, g_ald);
    cudaGetSymbolAddress((void**)&p_stats, g_stats);
    cudaGetSymbolAddress((void**)&p_scale, g_scale);
    cudaGetSymbolAddress((void**)&p_shift, g_shift);
    cudaGetSymbolAddress((void**)&p_cnt, g_cnt);
    cudaGetSymbolAddress((void**)&p_rs, g_rs);
    cudaGetSymbolAddress((void**)&p_cur, g_cur);
    cudaGetSymbolAddress((void**)&p_srcs, g_srcs);
    cudaGetSymbolAddress((void**)&p_ahi, g_ahi);
    cudaGetSymbolAddress((void**)&p_alo, g_alo);
    cudaGetSymbolAddress((void**)&p_wthi, g_wthi);
    cudaGetSymbolAddress((void**)&p_wtlo, g_wtlo);

    cudaFuncSetAttribute(k_wgemm, cudaFuncAttributeMaxDynamicSharedMemorySize, WG_SMEM);

    const int TB = 256;
    dim3 wg_grid(2, (NN + 127) / 128);
    dim3 gemm_grid_64(1, (NN + 63) / 64);
    int agg_blocks = (NN + 3) / 4;

    // stats regions: 0 = bn1(256ch), 1 = bn2(64ch), 2 = bn3, 3 = bn4
    float* st0 = p_stats;
    float* st1 = p_stats + 512;
    float* st2 = p_stats + 1024;
    float* st3 = p_stats + 1536;

    // ---- conv1 GEMM inputs + GEMM (launch #4 = profiled) ----
    k_cvt<<<(NN * 128 + TB - 1) / TB, TB>>>(x, p_ahi, p_alo, NN * 128);        // 1
    k_cvt_wt<<<(128 * 256 + TB - 1) / TB, TB>>>(W1, p_wthi, p_wtlo, 128, 256); // 2
    k_zeroi<<<(NN + TB - 1) / TB, TB>>>(p_cnt, NN);                            // 3
    k_wgemm<<<wg_grid, TB, WG_SMEM>>>(p_ahi, p_alo, p_wthi, p_wtlo, p_h,
                                      a1_src, a1_dst, p_als, p_ald,
                                      NN, 128, 256);                           // 4
    // ---- CSR build + stats zero ----
    k_count<<<(EE + TB - 1) / TB, TB>>>(ei, p_cnt);
    k_scan<<<1, 1024>>>(p_cnt, p_rs, p_cur);
    k_scatter<<<(EE + TB - 1) / TB, TB>>>(ei, p_cur, p_srcs);
    k_zerof<<<8, TB>>>(p_stats, 2048);

    // ---- conv1 fused softmax+aggregation ----
    k_aggf<false><<<agg_blocks, TB>>>(p_h, p_als, p_ald, p_rs, p_srcs, b1, p_agg);

    // ---- bn1 stats -> scale/shift (applied in conv2 A conversion) ----
    k_bnstats<<<(NN + 255) / 256, TB>>>(p_agg, st0, NN, 256, 256);
    k_bnprep<<<1, 256>>>(st0, bn1_g, bn1_b, p_scale, p_shift, NN, 256);

    // ---- conv2 ----
    k_cvt_bn<<<(NN * 256 + TB - 1) / TB, TB>>>(p_agg, p_scale, p_shift,
                                               p_ahi, p_alo, NN * 256);
    k_cvt_wt<<<(256 * 256 + TB - 1) / TB, TB>>>(W2, p_wthi, p_wtlo, 256, 256);
    k_wgemm<<<wg_grid, TB, WG_SMEM>>>(p_ahi, p_alo, p_wthi, p_wtlo, p_h,
                                      a2_src, a2_dst, p_als, p_ald,
                                      NN, 256, 256);
    k_aggf<true><<<agg_blocks, TB>>>(p_h, p_als, p_ald, p_rs, p_srcs, b2, p_s1);

    // ---- bn2 stats -> folded into lin1 (no relu) ----
    k_bnstats<<<(NN + 255) / 256, TB>>>(p_s1, st1, NN, 64, 256);
    k_gemm<<<gemm_grid_64, TB>>>(p_s1, lin1_W, lin1_b, p_s2, NN, 64, 64,
                                 st1, bn2_g, bn2_b, 0);

    // ---- bn3 stats -> folded into lin2 (relu) ----
    k_bnstats<<<(NN + 255) / 256, TB>>>(p_s2, st2, NN, 64, 256);
    k_gemm<<<gemm_grid_64, TB>>>(p_s2, lin2_W, lin2_b, p_s1, NN, 64, 64,
                                 st2, bn3_g, bn3_b, 1);

    // ---- bn4 stats -> fused bn4+relu+fin dot+sigmoid ----
    k_bnstats<<<(NN + 255) / 256, TB>>>(p_s1, st3, NN, 64, 256);
    k_bnfin<<<(NN + 7) / 8, TB>>>(p_s1, st3, bn4_g, bn4_b, fin_W, fin_b, out);
}

// round 12
// speedup vs baseline: 1.0055x; 1.0055x over previous
#include <cuda_runtime.h>
#include <cuda_bf16.h>
#include <mma.h>
#include <math.h>
#include <stdint.h>

using namespace nvcuda;

#define NN 50000
#define EE 800000
#define BN_EPS 1e-5f

// ---------------- scratch (static device globals; no runtime alloc) ----------------
__device__ float g_h[NN * 256];
__device__ float g_agg[NN * 256];
__device__ float g_s1[NN * 64];
__device__ float g_s2[NN * 64];
__device__ float g_als[NN * 4];
__device__ float g_ald[NN * 4];
__device__ float g_den[NN * 4];
__device__ float g_p[EE * 4];
__device__ int   g_cnt[NN];
__device__ int   g_rs[NN + 1];
__device__ int   g_cur[NN];
__device__ int   g_srcs[EE];
__device__ float g_stats[2048];      // 4 regions of 512
__device__ float g_scale[256];
__device__ float g_shift[256];
__device__ __nv_bfloat16 g_ahi[NN * 256];
__device__ __nv_bfloat16 g_alo[NN * 256];
__device__ __nv_bfloat16 g_wthi[256 * 256];
__device__ __nv_bfloat16 g_wtlo[256 * 256];

// ---------------- tiny utility kernels ----------------
__global__ void k_zeroi(int* __restrict__ p, int n) {
    int i = blockIdx.x * blockDim.x + threadIdx.x;
    if (i < n) p[i] = 0;
}
__global__ void k_zerof(float* __restrict__ p, int n) {
    int i = blockIdx.x * blockDim.x + threadIdx.x;
    if (i < n) p[i] = 0.f;
}

// ---------------- fp32 -> bf16 hi/lo split conversions ----------------
__global__ void k_cvt(const float* __restrict__ a, __nv_bfloat16* __restrict__ hi,
                      __nv_bfloat16* __restrict__ lo, int total) {
    int i = blockIdx.x * blockDim.x + threadIdx.x;
    if (i >= total) return;
    float v = a[i];
    __nv_bfloat16 h = __float2bfloat16(v);
    hi[i] = h;
    lo[i] = __float2bfloat16(v - __bfloat162float(h));
}

__global__ void k_cvt_bn(const float* __restrict__ a, const float* __restrict__ sc,
                         const float* __restrict__ sh, __nv_bfloat16* __restrict__ hi,
                         __nv_bfloat16* __restrict__ lo, int total) {
    int i = blockIdx.x * blockDim.x + threadIdx.x;
    if (i >= total) return;
    int c = i & 255;
    float v = fmaxf(fmaf(a[i], sc[c], sh[c]), 0.f);
    __nv_bfloat16 h = __float2bfloat16(v);
    hi[i] = h;
    lo[i] = __float2bfloat16(v - __bfloat162float(h));
}

// W [K,cout] -> transposed Wt [cout,K] hi/lo bf16
__global__ void k_cvt_wt(const float* __restrict__ w, __nv_bfloat16* __restrict__ hi,
                         __nv_bfloat16* __restrict__ lo, int K, int cout) {
    int i = blockIdx.x * blockDim.x + threadIdx.x;
    if (i >= K * cout) return;
    int k = i / cout;
    int c = i - k * cout;
    float v = w[i];
    __nv_bfloat16 h = __float2bfloat16(v);
    hi[c * K + k] = h;
    lo[c * K + k] = __float2bfloat16(v - __bfloat162float(h));
}

// ---------------- CSR build ----------------
__global__ void k_count(const int* __restrict__ ei, int* __restrict__ cnt) {
    int e = blockIdx.x * blockDim.x + threadIdx.x;
    if (e < EE) atomicAdd(&cnt[ei[EE + e]], 1);
}

// scan also initializes cur (= rs)
__global__ void k_scan(const int* __restrict__ cnt, int* __restrict__ rs,
                       int* __restrict__ cur) {
    __shared__ int sh[1024];
    int t = threadIdx.x;
    const int n = NN;
    int chunk = (n + 1023) >> 10;
    int b0 = t * chunk;
    int b1 = b0 + chunk; if (b1 > n) b1 = n; if (b0 > n) b0 = n;
    int local = 0;
    for (int i = b0; i < b1; i++) local += cnt[i];
    sh[t] = local;
    __syncthreads();
    for (int off = 1; off < 1024; off <<= 1) {
        int v = (t >= off) ? sh[t - off] : 0;
        __syncthreads();
        sh[t] += v;
        __syncthreads();
    }
    int base = sh[t] - local;
    for (int i = b0; i < b1; i++) { rs[i] = base; cur[i] = base; base += cnt[i]; }
    if (t == 1023) rs[n] = sh[1023];
}

__global__ void k_scatter(const int* __restrict__ ei, int* __restrict__ cur,
                          int* __restrict__ srcs) {
    int e = blockIdx.x * blockDim.x + threadIdx.x;
    if (e < EE) {
        int d = ei[EE + e];
        int pos = atomicAdd(&cur[d], 1);
        srcs[pos] = ei[e];
    }
}

// ================= WMMA bf16-split GEMM, cp.async double-buffered =================
#define WG_LD        40
#define WG_MAT       (128 * WG_LD)
#define WG_BUF       (4 * WG_MAT)
#define WG_BUF_BYTES (WG_BUF * 2)
#define WG_SMEM      (2 * WG_BUF_BYTES)

__device__ __forceinline__ void cp16(uint32_t dst, const void* src, int sz) {
    asm volatile("cp.async.ca.shared.global [%0], [%1], 16, %2;"
                 :: "r"(dst), "l"(src), "r"(sz));
}
__device__ __forceinline__ void cp_commit() {
    asm volatile("cp.async.commit_group;" ::: "memory");
}
template <int N>
__device__ __forceinline__ void cp_wait() {
    asm volatile("cp.async.wait_group %0;" :: "n"(N) : "memory");
}

__global__ void __launch_bounds__(256, 2)
k_wgemm(const __nv_bfloat16* __restrict__ Ahi, const __nv_bfloat16* __restrict__ Alo,
        const __nv_bfloat16* __restrict__ Bhi, const __nv_bfloat16* __restrict__ Blo,
        float* __restrict__ C, const float* __restrict__ asrc,
        const float* __restrict__ adst, float* __restrict__ als,
        float* __restrict__ ald, int n, int K, int cout) {
    extern __shared__ __align__(16) __nv_bfloat16 sm[];
    int tid = threadIdx.x;
    int wid = tid >> 5;
    int lane = tid & 31;
    int wm = wid >> 1;
    int wn = wid & 1;
    int row0 = blockIdx.y * 128;
    int col0 = blockIdx.x * 128;

    int r0i = tid >> 2,         c0i = (tid & 3) * 8;
    int r1i = (tid + 256) >> 2, c1i = (tid & 3) * 8;
    int gr0 = row0 + r0i, gr1 = row0 + r1i;
    int sza0 = (gr0 < n) ? 16 : 0;
    int sza1 = (gr1 < n) ? 16 : 0;
    int ar0 = (gr0 < n) ? gr0 : 0;
    int ar1 = (gr1 < n) ? gr1 : 0;

    uint32_t sbase = (uint32_t)__cvta_generic_to_shared(sm);
    uint32_t so0 = (uint32_t)((r0i * WG_LD + c0i) * 2);
    uint32_t so1 = (uint32_t)((r1i * WG_LD + c1i) * 2);
    const uint32_t MATB = WG_MAT * 2;

    int nch = K >> 5;

    auto issue = [&](int ch, int buf) {
        int k0 = ch << 5;
        uint32_t b = sbase + (uint32_t)buf * WG_BUF_BYTES;
        size_t a0 = (size_t)ar0 * K + k0 + c0i;
        size_t a1 = (size_t)ar1 * K + k0 + c1i;
        size_t b0 = (size_t)(col0 + r0i) * K + k0 + c0i;
        size_t b1 = (size_t)(col0 + r1i) * K + k0 + c1i;
        cp16(b + so0, &Ahi[a0], sza0);
        cp16(b + so1, &Ahi[a1], sza1);
        cp16(b + MATB + so0, &Alo[a0], sza0);
        cp16(b + MATB + so1, &Alo[a1], sza1);
        cp16(b + 2 * MATB + so0, &Bhi[b0], 16);
        cp16(b + 2 * MATB + so1, &Bhi[b1], 16);
        cp16(b + 3 * MATB + so0, &Blo[b0], 16);
        cp16(b + 3 * MATB + so1, &Blo[b1], 16);
    };

    issue(0, 0);
    cp_commit();

    wmma::fragment<wmma::accumulator, 16, 16, 16, float> acc[2][4];
#pragma unroll
    for (int i = 0; i < 2; i++)
#pragma unroll
        for (int j = 0; j < 4; j++) wmma::fill_fragment(acc[i][j], 0.f);

    for (int ch = 0; ch < nch; ch++) {
        if (ch + 1 < nch) {
            issue(ch + 1, (ch + 1) & 1);
            cp_commit();
            cp_wait<1>();
        } else {
            cp_wait<0>();
        }
        __syncthreads();
        int cur = (ch & 1) * WG_BUF;
#pragma unroll
        for (int ks = 0; ks < 2; ks++) {
            wmma::fragment<wmma::matrix_a, 16, 16, 16, __nv_bfloat16, wmma::row_major> ah[2], al[2];
            const __nv_bfloat16* pa = &sm[cur + (wm * 32) * WG_LD + ks * 16];
            wmma::load_matrix_sync(ah[0], pa, WG_LD);
            wmma::load_matrix_sync(ah[1], pa + 16 * WG_LD, WG_LD);
            wmma::load_matrix_sync(al[0], pa + WG_MAT, WG_LD);
            wmma::load_matrix_sync(al[1], pa + WG_MAT + 16 * WG_LD, WG_LD);
#pragma unroll
            for (int j = 0; j < 4; j++) {
                wmma::fragment<wmma::matrix_b, 16, 16, 16, __nv_bfloat16, wmma::col_major> bh, bl;
                const __nv_bfloat16* pb =
                    &sm[cur + 2 * WG_MAT + (wn * 64 + j * 16) * WG_LD + ks * 16];
                wmma::load_matrix_sync(bh, pb, WG_LD);
                wmma::load_matrix_sync(bl, pb + WG_MAT, WG_LD);
                wmma::mma_sync(acc[0][j], ah[0], bh, acc[0][j]);
                wmma::mma_sync(acc[0][j], ah[0], bl, acc[0][j]);
                wmma::mma_sync(acc[0][j], al[0], bh, acc[0][j]);
                wmma::mma_sync(acc[1][j], ah[1], bh, acc[1][j]);
                wmma::mma_sync(acc[1][j], ah[1], bl, acc[1][j]);
                wmma::mma_sync(acc[1][j], al[1], bh, acc[1][j]);
            }
        }
        __syncthreads();
    }

    // ---- epilogue: stage C tile in smem, write C coalesced, compute als/ald ----
    float* smC = reinterpret_cast<float*>(sm);
    const int CLD = 132;
#pragma unroll
    for (int i = 0; i < 2; i++)
#pragma unroll
        for (int j = 0; j < 4; j++)
            wmma::store_matrix_sync(smC + (wm * 32 + i * 16) * CLD + wn * 64 + j * 16,
                                    acc[i][j], CLD, wmma::mem_row_major);
    __syncthreads();

    for (int t = tid; t < 128 * 32; t += 256) {
        int r = t >> 5, c4 = (t & 31) * 4;
        int gr = row0 + r;
        if (gr < n)
            *reinterpret_cast<float4*>(&C[(size_t)gr * cout + col0 + c4]) =
                *reinterpret_cast<const float4*>(&smC[r * CLD + c4]);
    }

    int half = lane >> 4;
    int l16 = lane & 15;
    int head = blockIdx.x * 2 + half;
    float4 as4 = *reinterpret_cast<const float4*>(&asrc[head * 64 + l16 * 4]);
    float4 ad4 = *reinterpret_cast<const float4*>(&adst[head * 64 + l16 * 4]);
#pragma unroll
    for (int rr = 0; rr < 16; rr++) {
        int r = wid * 16 + rr;
        int gr = row0 + r;
        float4 v = *reinterpret_cast<const float4*>(&smC[r * CLD + half * 64 + l16 * 4]);
        float vs = v.x * as4.x + v.y * as4.y + v.z * as4.z + v.w * as4.w;
        float vd = v.x * ad4.x + v.y * ad4.y + v.z * ad4.z + v.w * ad4.w;
#pragma unroll
        for (int o = 8; o; o >>= 1) {
            vs += __shfl_xor_sync(0xffffffffu, vs, o);
            vd += __shfl_xor_sync(0xffffffffu, vd, o);
        }
        if (l16 == 0 && gr < n) {
            als[gr * 4 + head] = vs;
            ald[gr * 4 + head] = vd;
        }
    }
}

// ---------------- small GEMM (64-wide), fused bn prep (from stats) + relu on A ----
__global__ void k_gemm(const float* __restrict__ A, const float* __restrict__ W,
                       const float* __restrict__ bias, float* __restrict__ C,
                       int n, int K, int cout,
                       const float* __restrict__ stats, const float* __restrict__ bng,
                       const float* __restrict__ bnb, int dorelu) {
    __shared__ __align__(16) float As[16][68];
    __shared__ __align__(16) float Ws[16][64];
    __shared__ float ssc[64], ssh[64];
    int tid = threadIdx.x;
    int tx = tid & 15;
    int ty = tid >> 4;
    int row0 = blockIdx.y * 64;
    int col0 = blockIdx.x * 64;

    if (stats && tid < 64) {
        float invn = 1.f / (float)n;
        float mu = stats[tid] * invn;
        float var = stats[64 + tid] * invn - mu * mu;
        float sc = rsqrtf(var + BN_EPS) * bng[tid];
        ssc[tid] = sc;
        ssh[tid] = bnb[tid] - mu * sc;
    }
    __syncthreads();

    float acc[4][4] = {};
    for (int k0 = 0; k0 < K; k0 += 16) {
#pragma unroll
        for (int i = 0; i < 4; i++) {
            int idx = tid + i * 256;
            int kk = idx & 15;
            int m  = idx >> 4;
            int gr = row0 + m;
            float v = (gr < n) ? A[(size_t)gr * K + k0 + kk] : 0.f;
            if (stats) {
                v = fmaf(v, ssc[k0 + kk], ssh[k0 + kk]);
                if (dorelu) v = fmaxf(v, 0.f);
            }
            As[kk][m] = v;
        }
#pragma unroll
        for (int i = 0; i < 4; i++) {
            int idx = tid + i * 256;
            int col = idx & 63;
            int kk  = idx >> 6;
            Ws[kk][col] = W[(size_t)(k0 + kk) * cout + col0 + col];
        }
        __syncthreads();
#pragma unroll
        for (int kk = 0; kk < 16; kk++) {
            float4 ra = *reinterpret_cast<const float4*>(&As[kk][ty * 4]);
            float4 rb = *reinterpret_cast<const float4*>(&Ws[kk][tx * 4]);
            float a[4] = {ra.x, ra.y, ra.z, ra.w};
            float b[4] = {rb.x, rb.y, rb.z, rb.w};
#pragma unroll
            for (int i = 0; i < 4; i++)
#pragma unroll
                for (int j = 0; j < 4; j++)
                    acc[i][j] = fmaf(a[i], b[j], acc[i][j]);
        }
        __syncthreads();
    }
#pragma unroll
    for (int i = 0; i < 4; i++) {
        int gr = row0 + ty * 4 + i;
        if (gr >= n) continue;
#pragma unroll
        for (int j = 0; j < 4; j++) {
            int gc = col0 + tx * 4 + j;
            float v = acc[i][j];
            if (bias) v += bias[gc];
            C[(size_t)gr * cout + gc] = v;
        }
    }
}

// ---------------- single-pass softmax: p = exp(leaky(e)), den = sum p -------------
__global__ void k_softmax(const float* __restrict__ als, const float* __restrict__ ald,
                          const int* __restrict__ rs, const int* __restrict__ srcs,
                          float* __restrict__ pbuf, float* __restrict__ den) {
    int node = (blockIdx.x * blockDim.x + threadIdx.x) >> 5;
    int lane = threadIdx.x & 31;
    if (node >= NN) return;
    int beg = rs[node], end = rs[node + 1];
    float ad0 = ald[node * 4 + 0], ad1 = ald[node * 4 + 1];
    float ad2 = ald[node * 4 + 2], ad3 = ald[node * 4 + 3];
    float d0 = 0.f, d1 = 0.f, d2 = 0.f, d3 = 0.f;
    for (int j = beg + lane; j < end; j += 32) {
        int s = srcs[j];
        float e0 = als[s * 4 + 0] + ad0; e0 = e0 > 0.f ? e0 : 0.2f * e0;
        float e1 = als[s * 4 + 1] + ad1; e1 = e1 > 0.f ? e1 : 0.2f * e1;
        float e2 = als[s * 4 + 2] + ad2; e2 = e2 > 0.f ? e2 : 0.2f * e2;
        float e3 = als[s * 4 + 3] + ad3; e3 = e3 > 0.f ? e3 : 0.2f * e3;
        float p0 = __expf(e0); float p1 = __expf(e1);
        float p2 = __expf(e2); float p3 = __expf(e3);
        pbuf[j * 4 + 0] = p0; pbuf[j * 4 + 1] = p1;
        pbuf[j * 4 + 2] = p2; pbuf[j * 4 + 3] = p3;
        d0 += p0; d1 += p1; d2 += p2; d3 += p3;
    }
#pragma unroll
    for (int o = 16; o; o >>= 1) {
        d0 += __shfl_xor_sync(0xffffffffu, d0, o);
        d1 += __shfl_xor_sync(0xffffffffu, d1, o);
        d2 += __shfl_xor_sync(0xffffffffu, d2, o);
        d3 += __shfl_xor_sync(0xffffffffu, d3, o);
    }
    if (lane == 0) {
        den[node * 4 + 0] = d0; den[node * 4 + 1] = d1;
        den[node * 4 + 2] = d2; den[node * 4 + 3] = d3;
    }
}

// ---------------- aggregation: 4 nodes/block, 64 threads/node, float4 gathers ------
template <bool MEAN>
__global__ void k_agg4(const float* __restrict__ hbuf, const float* __restrict__ pbuf,
                       const float* __restrict__ den, const int* __restrict__ rs,
                       const int* __restrict__ srcs, const float* __restrict__ bias,
                       float* __restrict__ out) {
    int grp = threadIdx.x >> 6;
    int lt  = threadIdx.x & 63;
    int node = blockIdx.x * 4 + grp;
    __shared__ float sm[4][256];

    float4 acc = make_float4(0.f, 0.f, 0.f, 0.f);
    float d = 1.f;
    if (node < NN) {
        int h = lt >> 4;
        int beg = rs[node], end = rs[node + 1];
        int j = beg;
        for (; j + 1 < end; j += 2) {
            int s0 = srcs[j], s1 = srcs[j + 1];
            float p0 = pbuf[j * 4 + h];
            float p1 = pbuf[(j + 1) * 4 + h];
            float4 v0 = *reinterpret_cast<const float4*>(&hbuf[(size_t)s0 * 256 + lt * 4]);
            float4 v1 = *reinterpret_cast<const float4*>(&hbuf[(size_t)s1 * 256 + lt * 4]);
            acc.x = fmaf(v0.x, p0, fmaf(v1.x, p1, acc.x));
            acc.y = fmaf(v0.y, p0, fmaf(v1.y, p1, acc.y));
            acc.z = fmaf(v0.z, p0, fmaf(v1.z, p1, acc.z));
            acc.w = fmaf(v0.w, p0, fmaf(v1.w, p1, acc.w));
        }
        if (j < end) {
            int s0 = srcs[j];
            float p0 = pbuf[j * 4 + h];
            float4 v0 = *reinterpret_cast<const float4*>(&hbuf[(size_t)s0 * 256 + lt * 4]);
            acc.x = fmaf(v0.x, p0, acc.x);
            acc.y = fmaf(v0.y, p0, acc.y);
            acc.z = fmaf(v0.z, p0, acc.z);
            acc.w = fmaf(v0.w, p0, acc.w);
        }
        d = den[node * 4 + h] + 1e-16f;
    }
    float inv = 1.f / d;
    acc.x *= inv; acc.y *= inv; acc.z *= inv; acc.w *= inv;

    if (!MEAN) {
        if (node < NN) {
            float4 bb = *reinterpret_cast<const float4*>(&bias[lt * 4]);
            acc.x += bb.x; acc.y += bb.y; acc.z += bb.z; acc.w += bb.w;
            *reinterpret_cast<float4*>(&out[(size_t)node * 256 + lt * 4]) = acc;
        }
    } else {
        *reinterpret_cast<float4*>(&sm[grp][lt * 4]) = acc;
        __syncthreads();
        if (node < NN && lt < 16) {
            float4 o;
            float* row = sm[grp];
            int c = lt * 4;
            o.x = (row[c + 0] + row[c + 64] + row[c + 128] + row[c + 192]) * 0.25f + bias[c + 0];
            o.y = (row[c + 1] + row[c + 65] + row[c + 129] + row[c + 193]) * 0.25f + bias[c + 1];
            o.z = (row[c + 2] + row[c + 66] + row[c + 130] + row[c + 194]) * 0.25f + bias[c + 2];
            o.w = (row[c + 3] + row[c + 67] + row[c + 131] + row[c + 195]) * 0.25f + bias[c + 3];
            *reinterpret_cast<float4*>(&out[(size_t)node * 64 + c]) = o;
        }
    }
}

// ---------------- batchnorm stats ----------------
__global__ void k_bnstats(const float* __restrict__ x, float* __restrict__ stats,
                          int n, int C, int rowsPerBlk) {
    int c = threadIdx.x % C;
    int rl = threadIdx.x / C;
    int lanes = blockDim.x / C;
    int r0 = blockIdx.x * rowsPerBlk;
    int r1 = r0 + rowsPerBlk; if (r1 > n) r1 = n;
    float s = 0.f, s2 = 0.f;
    for (int r = r0 + rl; r < r1; r += lanes) {
        float v = x[(size_t)r * C + c];
        s += v; s2 += v * v;
    }
    __shared__ float sh[2][256];
    sh[0][threadIdx.x] = s; sh[1][threadIdx.x] = s2;
    __syncthreads();
    if (rl == 0) {
        for (int l = 1; l < lanes; l++) {
            s += sh[0][c + l * C]; s2 += sh[1][c + l * C];
        }
        atomicAdd(&stats[c], s);
        atomicAdd(&stats[C + c], s2);
    }
}

__global__ void k_bnprep(const float* __restrict__ stats, const float* __restrict__ g,
                         const float* __restrict__ b, float* __restrict__ scale,
                         float* __restrict__ shift, int n, int C) {
    int c = threadIdx.x + blockIdx.x * blockDim.x;
    if (c >= C) return;
    float invn = 1.f / (float)n;
    float mu = stats[c] * invn;
    float var = stats[C + c] * invn - mu * mu;
    float sc = rsqrtf(var + BN_EPS) * g[c];
    scale[c] = sc;
    shift[c] = b[c] - mu * sc;
}

// ---------------- fused bn4 + relu + final dot + sigmoid ----------------
__global__ void k_bnfin(const float* __restrict__ x, const float* __restrict__ stats,
                        const float* __restrict__ g, const float* __restrict__ b,
                        const float* __restrict__ w, const float* __restrict__ fb,
                        float* __restrict__ out) {
    int row = blockIdx.x * 8 + (threadIdx.x >> 5);
    int lane = threadIdx.x & 31;
    if (row >= NN) return;
    float invn = 1.f / (float)NN;
    float s = 0.f;
#pragma unroll
    for (int half = 0; half < 2; half++) {
        int c = lane + half * 32;
        float mu = stats[c] * invn;
        float var = stats[64 + c] * invn - mu * mu;
        float v = (x[(size_t)row * 64 + c] - mu) * rsqrtf(var + BN_EPS) * g[c] + b[c];
        v = fmaxf(v, 0.f);
        s = fmaf(v, w[c], s);
    }
#pragma unroll
    for (int o = 16; o; o >>= 1) s += __shfl_xor_sync(0xffffffffu, s, o);
    if (lane == 0) out[row] = 1.f / (1.f + __expf(-(s + fb[0])));
}

// ---------------- host launch ----------------
extern "C" void kernel_launch(void* const* d_in, const int* in_sizes, int n_in,
                              void* d_out, int out_size) {
    const float* x        = (const float*)d_in[0];
    const int*   ei       = (const int*)d_in[1];
    const float* W1       = (const float*)d_in[2];
    const float* a1_src   = (const float*)d_in[3];
    const float* a1_dst   = (const float*)d_in[4];
    const float* b1       = (const float*)d_in[5];
    const float* W2       = (const float*)d_in[6];
    const float* a2_src   = (const float*)d_in[7];
    const float* a2_dst   = (const float*)d_in[8];
    const float* b2       = (const float*)d_in[9];
    const float* bn1_g    = (const float*)d_in[10];
    const float* bn1_b    = (const float*)d_in[11];
    const float* bn2_g    = (const float*)d_in[12];
    const float* bn2_b    = (const float*)d_in[13];
    const float* bn3_g    = (const float*)d_in[14];
    const float* bn3_b    = (const float*)d_in[15];
    const float* bn4_g    = (const float*)d_in[16];
    const float* bn4_b    = (const float*)d_in[17];
    const float* lin1_W   = (const float*)d_in[18];
    const float* lin1_b   = (const float*)d_in[19];
    const float* lin2_W   = (const float*)d_in[20];
    const float* lin2_b   = (const float*)d_in[21];
    const float* fin_W    = (const float*)d_in[22];
    const float* fin_b    = (const float*)d_in[23];
    float* out            = (float*)d_out;

    float *p_h, *p_agg, *p_s1, *p_s2, *p_als, *p_ald, *p_den, *p_p, *p_stats;
    float *p_scale, *p_shift;
    int *p_cnt, *p_rs, *p_cur, *p_srcs;
    __nv_bfloat16 *p_ahi, *p_alo, *p_wthi, *p_wtlo;
    cudaGetSymbolAddress((void**)&p_h, g_h);
    cudaGetSymbolAddress((void**)&p_agg, g_agg);
    cudaGetSymbolAddress((void**)&p_s1, g_s1);
    cudaGetSymbolAddress((void**)&p_s2, g_s2);
    cudaGetSymbolAddress((void**)&p_als, g_als);
    cudaGetSymbolAddress((void**)&p_ald, g_ald);
    cudaGetSymbolAddress((void**)&p_den, g_den);
    cudaGetSymbolAddress((void**)&p_p, g_p);
    cudaGetSymbolAddress((void**)&p_stats, g_stats);
    cudaGetSymbolAddress((void**)&p_scale, g_scale);
    cudaGetSymbolAddress((void**)&p_shift, g_shift);
    cudaGetSymbolAddress((void**)&p_cnt, g_cnt);
    cudaGetSymbolAddress((void**)&p_rs, g_rs);
    cudaGetSymbolAddress((void**)&p_cur, g_cur);
    cudaGetSymbolAddress((void**)&p_srcs, g_srcs);
    cudaGetSymbolAddress((void**)&p_ahi, g_ahi);
    cudaGetSymbolAddress((void**)&p_alo, g_alo);
    cudaGetSymbolAddress((void**)&p_wthi, g_wthi);
    cudaGetSymbolAddress((void**)&p_wtlo, g_wtlo);

    cudaFuncSetAttribute(k_wgemm, cudaFuncAttributeMaxDynamicSharedMemorySize, WG_SMEM);

    const int TB = 256;
    dim3 wg_grid(2, (NN + 127) / 128);
    dim3 gemm_grid_64(1, (NN + 63) / 64);
    int agg_blocks = (NN + 3) / 4;

    // stats regions: 0 = bn1(256ch), 1 = bn2(64ch), 2 = bn3, 3 = bn4
    float* st0 = p_stats;
    float* st1 = p_stats + 512;
    float* st2 = p_stats + 1024;
    float* st3 = p_stats + 1536;

    // ---- conv1 GEMM inputs + GEMM (launch #4 = profiled) ----
    k_cvt<<<(NN * 128 + TB - 1) / TB, TB>>>(x, p_ahi, p_alo, NN * 128);        // 1
    k_cvt_wt<<<(128 * 256 + TB - 1) / TB, TB>>>(W1, p_wthi, p_wtlo, 128, 256); // 2
    k_zeroi<<<(NN + TB - 1) / TB, TB>>>(p_cnt, NN);                            // 3
    k_wgemm<<<wg_grid, TB, WG_SMEM>>>(p_ahi, p_alo, p_wthi, p_wtlo, p_h,
                                      a1_src, a1_dst, p_als, p_ald,
                                      NN, 128, 256);                           // 4
    // ---- CSR build + stats zero ----
    k_count<<<(EE + TB - 1) / TB, TB>>>(ei, p_cnt);
    k_scan<<<1, 1024>>>(p_cnt, p_rs, p_cur);
    k_scatter<<<(EE + TB - 1) / TB, TB>>>(ei, p_cur, p_srcs);
    k_zerof<<<8, TB>>>(p_stats, 2048);

    // ---- conv1 softmax (single pass) + aggregation ----
    k_softmax<<<(NN * 32 + TB - 1) / TB, TB>>>(p_als, p_ald, p_rs, p_srcs, p_p, p_den);
    k_agg4<false><<<agg_blocks, TB>>>(p_h, p_p, p_den, p_rs, p_srcs, b1, p_agg);

    // ---- bn1 stats -> scale/shift (applied in conv2 A conversion) ----
    k_bnstats<<<(NN + 255) / 256, TB>>>(p_agg, st0, NN, 256, 256);
    k_bnprep<<<1, 256>>>(st0, bn1_g, bn1_b, p_scale, p_shift, NN, 256);

    // ---- conv2 ----
    k_cvt_bn<<<(NN * 256 + TB - 1) / TB, TB>>>(p_agg, p_scale, p_shift,
                                               p_ahi, p_alo, NN * 256);
    k_cvt_wt<<<(256 * 256 + TB - 1) / TB, TB>>>(W2, p_wthi, p_wtlo, 256, 256);
    k_wgemm<<<wg_grid, TB, WG_SMEM>>>(p_ahi, p_alo, p_wthi, p_wtlo, p_h,
                                      a2_src, a2_dst, p_als, p_ald,
                                      NN, 256, 256);
    k_softmax<<<(NN * 32 + TB - 1) / TB, TB>>>(p_als, p_ald, p_rs, p_srcs, p_p, p_den);
    k_agg4<true><<<agg_blocks, TB>>>(p_h, p_p, p_den, p_rs, p_srcs, b2, p_s1);

    // ---- bn2 stats -> folded into lin1 (no relu) ----
    k_bnstats<<<(NN + 255) / 256, TB>>>(p_s1, st1, NN, 64, 256);
    k_gemm<<<gemm_grid_64, TB>>>(p_s1, lin1_W, lin1_b, p_s2, NN, 64, 64,
                                 st1, bn2_g, bn2_b, 0);

    // ---- bn3 stats -> folded into lin2 (relu) ----
    k_bnstats<<<(NN + 255) / 256, TB>>>(p_s2, st2, NN, 64, 256);
    k_gemm<<<gemm_grid_64, TB>>>(p_s2, lin2_W, lin2_b, p_s1, NN, 64, 64,
                                 st2, bn3_g, bn3_b, 1);

    // ---- bn4 stats -> fused bn4+relu+fin dot+sigmoid ----
    k_bnstats<<<(NN + 255) / 256, TB>>>(p_s1, st3, NN, 64, 256);
    k_bnfin<<<(NN + 7) / 8, TB>>>(p_s1, st3, bn4_g, bn4_b, fin_W, fin_b, out);
}

// round 13
// speedup vs baseline: 1.0719x; 1.0661x over previous
#include <cuda_runtime.h>
#include <cuda_bf16.h>
#include <mma.h>
#include <math.h>
#include <stdint.h>

using namespace nvcuda;

#define NN 50000
#define EE 800000
#define BN_EPS 1e-5f

// ---------------- scratch (static device globals; no runtime alloc) ----------------
__device__ float g_h[NN * 256];
__device__ float g_agg[NN * 256];
__device__ float g_s1[NN * 64];
__device__ float g_s2[NN * 64];
__device__ float g_als[NN * 4];
__device__ float g_ald[NN * 4];
__device__ float g_den[NN * 4];
__device__ float g_p[EE * 4];
__device__ int   g_cnt[NN];
__device__ int   g_rs[NN + 1];
__device__ int   g_cur[NN];
__device__ int   g_srcs[EE];
__device__ float g_stats[2048];
__device__ float g_scale[256];
__device__ float g_shift[256];
__device__ __nv_bfloat16 g_ahi[NN * 256];
__device__ __nv_bfloat16 g_alo[NN * 256];
__device__ __nv_bfloat16 g_wthi[256 * 256];
__device__ __nv_bfloat16 g_wtlo[256 * 256];
__device__ __nv_bfloat16 g_wthi2[256 * 256];
__device__ __nv_bfloat16 g_wtlo2[256 * 256];

// ---------------- tiny utility kernels ----------------
__global__ void k_zeroi(int* __restrict__ p, int n) {
    int i = blockIdx.x * blockDim.x + threadIdx.x;
    if (i < n) p[i] = 0;
}
__global__ void k_zerof(float* __restrict__ p, int n) {
    int i = blockIdx.x * blockDim.x + threadIdx.x;
    if (i < n) p[i] = 0.f;
}

// ---------------- fp32 -> bf16 hi/lo split conversions ----------------
__global__ void k_cvt(const float* __restrict__ a, __nv_bfloat16* __restrict__ hi,
                      __nv_bfloat16* __restrict__ lo, int total) {
    int i = blockIdx.x * blockDim.x + threadIdx.x;
    if (i >= total) return;
    float v = a[i];
    __nv_bfloat16 h = __float2bfloat16(v);
    hi[i] = h;
    lo[i] = __float2bfloat16(v - __bfloat162float(h));
}

__global__ void k_cvt_bn(const float* __restrict__ a, const float* __restrict__ sc,
                         const float* __restrict__ sh, __nv_bfloat16* __restrict__ hi,
                         __nv_bfloat16* __restrict__ lo, int total) {
    int i = blockIdx.x * blockDim.x + threadIdx.x;
    if (i >= total) return;
    int c = i & 255;
    float v = fmaxf(fmaf(a[i], sc[c], sh[c]), 0.f);
    __nv_bfloat16 h = __float2bfloat16(v);
    hi[i] = h;
    lo[i] = __float2bfloat16(v - __bfloat162float(h));
}

// W [K,cout] -> transposed Wt [cout,K] hi/lo bf16
__global__ void k_cvt_wt(const float* __restrict__ w, __nv_bfloat16* __restrict__ hi,
                         __nv_bfloat16* __restrict__ lo, int K, int cout) {
    int i = blockIdx.x * blockDim.x + threadIdx.x;
    if (i >= K * cout) return;
    int k = i / cout;
    int c = i - k * cout;
    float v = w[i];
    __nv_bfloat16 h = __float2bfloat16(v);
    hi[c * K + k] = h;
    lo[c * K + k] = __float2bfloat16(v - __bfloat162float(h));
}

// ---------------- CSR build ----------------
__global__ void k_count(const int* __restrict__ ei, int* __restrict__ cnt) {
    int e = blockIdx.x * blockDim.x + threadIdx.x;
    if (e < EE) atomicAdd(&cnt[ei[EE + e]], 1);
}

__global__ void k_scan(const int* __restrict__ cnt, int* __restrict__ rs,
                       int* __restrict__ cur) {
    __shared__ int sh[1024];
    int t = threadIdx.x;
    const int n = NN;
    int chunk = (n + 1023) >> 10;
    int b0 = t * chunk;
    int b1 = b0 + chunk; if (b1 > n) b1 = n; if (b0 > n) b0 = n;
    int local = 0;
    for (int i = b0; i < b1; i++) local += cnt[i];
    sh[t] = local;
    __syncthreads();
    for (int off = 1; off < 1024; off <<= 1) {
        int v = (t >= off) ? sh[t - off] : 0;
        __syncthreads();
        sh[t] += v;
        __syncthreads();
    }
    int base = sh[t] - local;
    for (int i = b0; i < b1; i++) { rs[i] = base; cur[i] = base; base += cnt[i]; }
    if (t == 1023) rs[n] = sh[1023];
}

__global__ void k_scatter(const int* __restrict__ ei, int* __restrict__ cur,
                          int* __restrict__ srcs) {
    int e = blockIdx.x * blockDim.x + threadIdx.x;
    if (e < EE) {
        int d = ei[EE + e];
        int pos = atomicAdd(&cur[d], 1);
        srcs[pos] = ei[e];
    }
}

// ================= WMMA bf16-split GEMM, cp.async double-buffered =================
#define WG_LD        40
#define WG_MAT       (128 * WG_LD)
#define WG_BUF       (4 * WG_MAT)
#define WG_BUF_BYTES (WG_BUF * 2)
#define WG_SMEM      (2 * WG_BUF_BYTES)

__device__ __forceinline__ void cp16(uint32_t dst, const void* src, int sz) {
    asm volatile("cp.async.ca.shared.global [%0], [%1], 16, %2;"
                 :: "r"(dst), "l"(src), "r"(sz));
}
__device__ __forceinline__ void cp_commit() {
    asm volatile("cp.async.commit_group;" ::: "memory");
}
template <int N>
__device__ __forceinline__ void cp_wait() {
    asm volatile("cp.async.wait_group %0;" :: "n"(N) : "memory");
}

__global__ void __launch_bounds__(256, 2)
k_wgemm(const __nv_bfloat16* __restrict__ Ahi, const __nv_bfloat16* __restrict__ Alo,
        const __nv_bfloat16* __restrict__ Bhi, const __nv_bfloat16* __restrict__ Blo,
        float* __restrict__ C, const float* __restrict__ asrc,
        const float* __restrict__ adst, float* __restrict__ als,
        float* __restrict__ ald, int n, int K, int cout) {
    extern __shared__ __align__(16) __nv_bfloat16 sm[];
    int tid = threadIdx.x;
    int wid = tid >> 5;
    int lane = tid & 31;
    int wm = wid >> 1;
    int wn = wid & 1;
    int row0 = blockIdx.y * 128;
    int col0 = blockIdx.x * 128;

    int r0i = tid >> 2,         c0i = (tid & 3) * 8;
    int r1i = (tid + 256) >> 2, c1i = (tid & 3) * 8;
    int gr0 = row0 + r0i, gr1 = row0 + r1i;
    int sza0 = (gr0 < n) ? 16 : 0;
    int sza1 = (gr1 < n) ? 16 : 0;
    int ar0 = (gr0 < n) ? gr0 : 0;
    int ar1 = (gr1 < n) ? gr1 : 0;

    uint32_t sbase = (uint32_t)__cvta_generic_to_shared(sm);
    uint32_t so0 = (uint32_t)((r0i * WG_LD + c0i) * 2);
    uint32_t so1 = (uint32_t)((r1i * WG_LD + c1i) * 2);
    const uint32_t MATB = WG_MAT * 2;

    int nch = K >> 5;

    auto issue = [&](int ch, int buf) {
        int k0 = ch << 5;
        uint32_t b = sbase + (uint32_t)buf * WG_BUF_BYTES;
        size_t a0 = (size_t)ar0 * K + k0 + c0i;
        size_t a1 = (size_t)ar1 * K + k0 + c1i;
        size_t b0 = (size_t)(col0 + r0i) * K + k0 + c0i;
        size_t b1 = (size_t)(col0 + r1i) * K + k0 + c1i;
        cp16(b + so0, &Ahi[a0], sza0);
        cp16(b + so1, &Ahi[a1], sza1);
        cp16(b + MATB + so0, &Alo[a0], sza0);
        cp16(b + MATB + so1, &Alo[a1], sza1);
        cp16(b + 2 * MATB + so0, &Bhi[b0], 16);
        cp16(b + 2 * MATB + so1, &Bhi[b1], 16);
        cp16(b + 3 * MATB + so0, &Blo[b0], 16);
        cp16(b + 3 * MATB + so1, &Blo[b1], 16);
    };

    issue(0, 0);
    cp_commit();

    wmma::fragment<wmma::accumulator, 16, 16, 16, float> acc[2][4];
#pragma unroll
    for (int i = 0; i < 2; i++)
#pragma unroll
        for (int j = 0; j < 4; j++) wmma::fill_fragment(acc[i][j], 0.f);

    for (int ch = 0; ch < nch; ch++) {
        if (ch + 1 < nch) {
            issue(ch + 1, (ch + 1) & 1);
            cp_commit();
            cp_wait<1>();
        } else {
            cp_wait<0>();
        }
        __syncthreads();
        int cur = (ch & 1) * WG_BUF;
#pragma unroll
        for (int ks = 0; ks < 2; ks++) {
            wmma::fragment<wmma::matrix_a, 16, 16, 16, __nv_bfloat16, wmma::row_major> ah[2], al[2];
            const __nv_bfloat16* pa = &sm[cur + (wm * 32) * WG_LD + ks * 16];
            wmma::load_matrix_sync(ah[0], pa, WG_LD);
            wmma::load_matrix_sync(ah[1], pa + 16 * WG_LD, WG_LD);
            wmma::load_matrix_sync(al[0], pa + WG_MAT, WG_LD);
            wmma::load_matrix_sync(al[1], pa + WG_MAT + 16 * WG_LD, WG_LD);
#pragma unroll
            for (int j = 0; j < 4; j++) {
                wmma::fragment<wmma::matrix_b, 16, 16, 16, __nv_bfloat16, wmma::col_major> bh, bl;
                const __nv_bfloat16* pb =
                    &sm[cur + 2 * WG_MAT + (wn * 64 + j * 16) * WG_LD + ks * 16];
                wmma::load_matrix_sync(bh, pb, WG_LD);
                wmma::load_matrix_sync(bl, pb + WG_MAT, WG_LD);
                wmma::mma_sync(acc[0][j], ah[0], bh, acc[0][j]);
                wmma::mma_sync(acc[0][j], ah[0], bl, acc[0][j]);
                wmma::mma_sync(acc[0][j], al[0], bh, acc[0][j]);
                wmma::mma_sync(acc[1][j], ah[1], bh, acc[1][j]);
                wmma::mma_sync(acc[1][j], ah[1], bl, acc[1][j]);
                wmma::mma_sync(acc[1][j], al[1], bh, acc[1][j]);
            }
        }
        __syncthreads();
    }

    // ---- epilogue: stage C tile in smem, write C coalesced, compute als/ald ----
    float* smC = reinterpret_cast<float*>(sm);
    const int CLD = 132;
#pragma unroll
    for (int i = 0; i < 2; i++)
#pragma unroll
        for (int j = 0; j < 4; j++)
            wmma::store_matrix_sync(smC + (wm * 32 + i * 16) * CLD + wn * 64 + j * 16,
                                    acc[i][j], CLD, wmma::mem_row_major);
    __syncthreads();

    for (int t = tid; t < 128 * 32; t += 256) {
        int r = t >> 5, c4 = (t & 31) * 4;
        int gr = row0 + r;
        if (gr < n)
            *reinterpret_cast<float4*>(&C[(size_t)gr * cout + col0 + c4]) =
                *reinterpret_cast<const float4*>(&smC[r * CLD + c4]);
    }

    int half = lane >> 4;
    int l16 = lane & 15;
    int head = blockIdx.x * 2 + half;
    float4 as4 = *reinterpret_cast<const float4*>(&asrc[head * 64 + l16 * 4]);
    float4 ad4 = *reinterpret_cast<const float4*>(&adst[head * 64 + l16 * 4]);
#pragma unroll
    for (int rr = 0; rr < 16; rr++) {
        int r = wid * 16 + rr;
        int gr = row0 + r;
        float4 v = *reinterpret_cast<const float4*>(&smC[r * CLD + half * 64 + l16 * 4]);
        float vs = v.x * as4.x + v.y * as4.y + v.z * as4.z + v.w * as4.w;
        float vd = v.x * ad4.x + v.y * ad4.y + v.z * ad4.z + v.w * ad4.w;
#pragma unroll
        for (int o = 8; o; o >>= 1) {
            vs += __shfl_xor_sync(0xffffffffu, vs, o);
            vd += __shfl_xor_sync(0xffffffffu, vd, o);
        }
        if (l16 == 0 && gr < n) {
            als[gr * 4 + head] = vs;
            ald[gr * 4 + head] = vd;
        }
    }
}

// ---------------- small GEMM (64-wide), fused bn prep (from stats) + relu on A ----
__global__ void k_gemm(const float* __restrict__ A, const float* __restrict__ W,
                       const float* __restrict__ bias, float* __restrict__ C,
                       int n, int K, int cout,
                       const float* __restrict__ stats, const float* __restrict__ bng,
                       const float* __restrict__ bnb, int dorelu) {
    __shared__ __align__(16) float As[16][68];
    __shared__ __align__(16) float Ws[16][64];
    __shared__ float ssc[64], ssh[64];
    int tid = threadIdx.x;
    int tx = tid & 15;
    int ty = tid >> 4;
    int row0 = blockIdx.y * 64;
    int col0 = blockIdx.x * 64;

    if (stats && tid < 64) {
        float invn = 1.f / (float)n;
        float mu = stats[tid] * invn;
        float var = stats[64 + tid] * invn - mu * mu;
        float sc = rsqrtf(var + BN_EPS) * bng[tid];
        ssc[tid] = sc;
        ssh[tid] = bnb[tid] - mu * sc;
    }
    __syncthreads();

    float acc[4][4] = {};
    for (int k0 = 0; k0 < K; k0 += 16) {
#pragma unroll
        for (int i = 0; i < 4; i++) {
            int idx = tid + i * 256;
            int kk = idx & 15;
            int m  = idx >> 4;
            int gr = row0 + m;
            float v = (gr < n) ? A[(size_t)gr * K + k0 + kk] : 0.f;
            if (stats) {
                v = fmaf(v, ssc[k0 + kk], ssh[k0 + kk]);
                if (dorelu) v = fmaxf(v, 0.f);
            }
            As[kk][m] = v;
        }
#pragma unroll
        for (int i = 0; i < 4; i++) {
            int idx = tid + i * 256;
            int col = idx & 63;
            int kk  = idx >> 6;
            Ws[kk][col] = W[(size_t)(k0 + kk) * cout + col0 + col];
        }
        __syncthreads();
#pragma unroll
        for (int kk = 0; kk < 16; kk++) {
            float4 ra = *reinterpret_cast<const float4*>(&As[kk][ty * 4]);
            float4 rb = *reinterpret_cast<const float4*>(&Ws[kk][tx * 4]);
            float a[4] = {ra.x, ra.y, ra.z, ra.w};
            float b[4] = {rb.x, rb.y, rb.z, rb.w};
#pragma unroll
            for (int i = 0; i < 4; i++)
#pragma unroll
                for (int j = 0; j < 4; j++)
                    acc[i][j] = fmaf(a[i], b[j], acc[i][j]);
        }
        __syncthreads();
    }
#pragma unroll
    for (int i = 0; i < 4; i++) {
        int gr = row0 + ty * 4 + i;
        if (gr >= n) continue;
#pragma unroll
        for (int j = 0; j < 4; j++) {
            int gc = col0 + tx * 4 + j;
            float v = acc[i][j];
            if (bias) v += bias[gc];
            C[(size_t)gr * cout + gc] = v;
        }
    }
}

// ---------------- single-pass softmax ----------------
__global__ void k_softmax(const float* __restrict__ als, const float* __restrict__ ald,
                          const int* __restrict__ rs, const int* __restrict__ srcs,
                          float* __restrict__ pbuf, float* __restrict__ den) {
    int node = (blockIdx.x * blockDim.x + threadIdx.x) >> 5;
    int lane = threadIdx.x & 31;
    if (node >= NN) return;
    int beg = rs[node], end = rs[node + 1];
    float ad0 = ald[node * 4 + 0], ad1 = ald[node * 4 + 1];
    float ad2 = ald[node * 4 + 2], ad3 = ald[node * 4 + 3];
    float d0 = 0.f, d1 = 0.f, d2 = 0.f, d3 = 0.f;
    for (int j = beg + lane; j < end; j += 32) {
        int s = srcs[j];
        float e0 = als[s * 4 + 0] + ad0; e0 = e0 > 0.f ? e0 : 0.2f * e0;
        float e1 = als[s * 4 + 1] + ad1; e1 = e1 > 0.f ? e1 : 0.2f * e1;
        float e2 = als[s * 4 + 2] + ad2; e2 = e2 > 0.f ? e2 : 0.2f * e2;
        float e3 = als[s * 4 + 3] + ad3; e3 = e3 > 0.f ? e3 : 0.2f * e3;
        float p0 = __expf(e0); float p1 = __expf(e1);
        float p2 = __expf(e2); float p3 = __expf(e3);
        pbuf[j * 4 + 0] = p0; pbuf[j * 4 + 1] = p1;
        pbuf[j * 4 + 2] = p2; pbuf[j * 4 + 3] = p3;
        d0 += p0; d1 += p1; d2 += p2; d3 += p3;
    }
#pragma unroll
    for (int o = 16; o; o >>= 1) {
        d0 += __shfl_xor_sync(0xffffffffu, d0, o);
        d1 += __shfl_xor_sync(0xffffffffu, d1, o);
        d2 += __shfl_xor_sync(0xffffffffu, d2, o);
        d3 += __shfl_xor_sync(0xffffffffu, d3, o);
    }
    if (lane == 0) {
        den[node * 4 + 0] = d0; den[node * 4 + 1] = d1;
        den[node * 4 + 2] = d2; den[node * 4 + 3] = d3;
    }
}

// ---------------- aggregation: 4 nodes/block, 64 threads/node, unroll-4 gathers ----
template <bool MEAN>
__global__ void k_agg4(const float* __restrict__ hbuf, const float* __restrict__ pbuf,
                       const float* __restrict__ den, const int* __restrict__ rs,
                       const int* __restrict__ srcs, const float* __restrict__ bias,
                       float* __restrict__ out) {
    int grp = threadIdx.x >> 6;
    int lt  = threadIdx.x & 63;
    int node = blockIdx.x * 4 + grp;
    __shared__ float sm[4][256];

    float4 acc = make_float4(0.f, 0.f, 0.f, 0.f);
    float d = 1.f;
    if (node < NN) {
        int h = lt >> 4;
        int beg = rs[node], end = rs[node + 1];
        int j = beg;
        for (; j + 3 < end; j += 4) {
            int s0 = srcs[j], s1 = srcs[j + 1], s2 = srcs[j + 2], s3 = srcs[j + 3];
            float p0 = pbuf[j * 4 + h];
            float p1 = pbuf[(j + 1) * 4 + h];
            float p2 = pbuf[(j + 2) * 4 + h];
            float p3 = pbuf[(j + 3) * 4 + h];
            float4 v0 = *reinterpret_cast<const float4*>(&hbuf[(size_t)s0 * 256 + lt * 4]);
            float4 v1 = *reinterpret_cast<const float4*>(&hbuf[(size_t)s1 * 256 + lt * 4]);
            float4 v2 = *reinterpret_cast<const float4*>(&hbuf[(size_t)s2 * 256 + lt * 4]);
            float4 v3 = *reinterpret_cast<const float4*>(&hbuf[(size_t)s3 * 256 + lt * 4]);
            acc.x = fmaf(v0.x, p0, fmaf(v1.x, p1, fmaf(v2.x, p2, fmaf(v3.x, p3, acc.x))));
            acc.y = fmaf(v0.y, p0, fmaf(v1.y, p1, fmaf(v2.y, p2, fmaf(v3.y, p3, acc.y))));
            acc.z = fmaf(v0.z, p0, fmaf(v1.z, p1, fmaf(v2.z, p2, fmaf(v3.z, p3, acc.z))));
            acc.w = fmaf(v0.w, p0, fmaf(v1.w, p1, fmaf(v2.w, p2, fmaf(v3.w, p3, acc.w))));
        }
        for (; j < end; j++) {
            int s0 = srcs[j];
            float p0 = pbuf[j * 4 + h];
            float4 v0 = *reinterpret_cast<const float4*>(&hbuf[(size_t)s0 * 256 + lt * 4]);
            acc.x = fmaf(v0.x, p0, acc.x);
            acc.y = fmaf(v0.y, p0, acc.y);
            acc.z = fmaf(v0.z, p0, acc.z);
            acc.w = fmaf(v0.w, p0, acc.w);
        }
        d = den[node * 4 + h] + 1e-16f;
    }
    float inv = 1.f / d;
    acc.x *= inv; acc.y *= inv; acc.z *= inv; acc.w *= inv;

    if (!MEAN) {
        if (node < NN) {
            float4 bb = *reinterpret_cast<const float4*>(&bias[lt * 4]);
            acc.x += bb.x; acc.y += bb.y; acc.z += bb.z; acc.w += bb.w;
            *reinterpret_cast<float4*>(&out[(size_t)node * 256 + lt * 4]) = acc;
        }
    } else {
        *reinterpret_cast<float4*>(&sm[grp][lt * 4]) = acc;
        __syncthreads();
        if (node < NN && lt < 16) {
            float4 o;
            float* row = sm[grp];
            int c = lt * 4;
            o.x = (row[c + 0] + row[c + 64] + row[c + 128] + row[c + 192]) * 0.25f + bias[c + 0];
            o.y = (row[c + 1] + row[c + 65] + row[c + 129] + row[c + 193]) * 0.25f + bias[c + 1];
            o.z = (row[c + 2] + row[c + 66] + row[c + 130] + row[c + 194]) * 0.25f + bias[c + 2];
            o.w = (row[c + 3] + row[c + 67] + row[c + 131] + row[c + 195]) * 0.25f + bias[c + 3];
            *reinterpret_cast<float4*>(&out[(size_t)node * 64 + c]) = o;
        }
    }
}

// ---------------- batchnorm stats ----------------
__global__ void k_bnstats(const float* __restrict__ x, float* __restrict__ stats,
                          int n, int C, int rowsPerBlk) {
    int c = threadIdx.x % C;
    int rl = threadIdx.x / C;
    int lanes = blockDim.x / C;
    int r0 = blockIdx.x * rowsPerBlk;
    int r1 = r0 + rowsPerBlk; if (r1 > n) r1 = n;
    float s = 0.f, s2 = 0.f;
    for (int r = r0 + rl; r < r1; r += lanes) {
        float v = x[(size_t)r * C + c];
        s += v; s2 += v * v;
    }
    __shared__ float sh[2][256];
    sh[0][threadIdx.x] = s; sh[1][threadIdx.x] = s2;
    __syncthreads();
    if (rl == 0) {
        for (int l = 1; l < lanes; l++) {
            s += sh[0][c + l * C]; s2 += sh[1][c + l * C];
        }
        atomicAdd(&stats[c], s);
        atomicAdd(&stats[C + c], s2);
    }
}

__global__ void k_bnprep(const float* __restrict__ stats, const float* __restrict__ g,
                         const float* __restrict__ b, float* __restrict__ scale,
                         float* __restrict__ shift, int n, int C) {
    int c = threadIdx.x + blockIdx.x * blockDim.x;
    if (c >= C) return;
    float invn = 1.f / (float)n;
    float mu = stats[c] * invn;
    float var = stats[C + c] * invn - mu * mu;
    float sc = rsqrtf(var + BN_EPS) * g[c];
    scale[c] = sc;
    shift[c] = b[c] - mu * sc;
}

// ---------------- fused bn4 + relu + final dot + sigmoid ----------------
__global__ void k_bnfin(const float* __restrict__ x, const float* __restrict__ stats,
                        const float* __restrict__ g, const float* __restrict__ b,
                        const float* __restrict__ w, const float* __restrict__ fb,
                        float* __restrict__ out) {
    int row = blockIdx.x * 8 + (threadIdx.x >> 5);
    int lane = threadIdx.x & 31;
    if (row >= NN) return;
    float invn = 1.f / (float)NN;
    float s = 0.f;
#pragma unroll
    for (int half = 0; half < 2; half++) {
        int c = lane + half * 32;
        float mu = stats[c] * invn;
        float var = stats[64 + c] * invn - mu * mu;
        float v = (x[(size_t)row * 64 + c] - mu) * rsqrtf(var + BN_EPS) * g[c] + b[c];
        v = fmaxf(v, 0.f);
        s = fmaf(v, w[c], s);
    }
#pragma unroll
    for (int o = 16; o; o >>= 1) s += __shfl_xor_sync(0xffffffffu, s, o);
    if (lane == 0) out[row] = 1.f / (1.f + __expf(-(s + fb[0])));
}

// ---------------- host launch ----------------
extern "C" void kernel_launch(void* const* d_in, const int* in_sizes, int n_in,
                              void* d_out, int out_size) {
    const float* x        = (const float*)d_in[0];
    const int*   ei       = (const int*)d_in[1];
    const float* W1       = (const float*)d_in[2];
    const float* a1_src   = (const float*)d_in[3];
    const float* a1_dst   = (const float*)d_in[4];
    const float* b1       = (const float*)d_in[5];
    const float* W2       = (const float*)d_in[6];
    const float* a2_src   = (const float*)d_in[7];
    const float* a2_dst   = (const float*)d_in[8];
    const float* b2       = (const float*)d_in[9];
    const float* bn1_g    = (const float*)d_in[10];
    const float* bn1_b    = (const float*)d_in[11];
    const float* bn2_g    = (const float*)d_in[12];
    const float* bn2_b    = (const float*)d_in[13];
    const float* bn3_g    = (const float*)d_in[14];
    const float* bn3_b    = (const float*)d_in[15];
    const float* bn4_g    = (const float*)d_in[16];
    const float* bn4_b    = (const float*)d_in[17];
    const float* lin1_W   = (const float*)d_in[18];
    const float* lin1_b   = (const float*)d_in[19];
    const float* lin2_W   = (const float*)d_in[20];
    const float* lin2_b   = (const float*)d_in[21];
    const float* fin_W    = (const float*)d_in[22];
    const float* fin_b    = (const float*)d_in[23];
    float* out            = (float*)d_out;

    float *p_h, *p_agg, *p_s1, *p_s2, *p_als, *p_ald, *p_den, *p_p, *p_stats;
    float *p_scale, *p_shift;
    int *p_cnt, *p_rs, *p_cur, *p_srcs;
    __nv_bfloat16 *p_ahi, *p_alo, *p_wthi, *p_wtlo, *p_wthi2, *p_wtlo2;
    cudaGetSymbolAddress((void**)&p_h, g_h);
    cudaGetSymbolAddress((void**)&p_agg, g_agg);
    cudaGetSymbolAddress((void**)&p_s1, g_s1);
    cudaGetSymbolAddress((void**)&p_s2, g_s2);
    cudaGetSymbolAddress((void**)&p_als, g_als);
    cudaGetSymbolAddress((void**)&p_ald, g_ald);
    cudaGetSymbolAddress((void**)&p_den, g_den);
    cudaGetSymbolAddress((void**)&p_p, g_p);
    cudaGetSymbolAddress((void**)&p_stats, g_stats);
    cudaGetSymbolAddress((void**)&p_scale, g_scale);
    cudaGetSymbolAddress((void**)&p_shift, g_shift);
    cudaGetSymbolAddress((void**)&p_cnt, g_cnt);
    cudaGetSymbolAddress((void**)&p_rs, g_rs);
    cudaGetSymbolAddress((void**)&p_cur, g_cur);
    cudaGetSymbolAddress((void**)&p_srcs, g_srcs);
    cudaGetSymbolAddress((void**)&p_ahi, g_ahi);
    cudaGetSymbolAddress((void**)&p_alo, g_alo);
    cudaGetSymbolAddress((void**)&p_wthi, g_wthi);
    cudaGetSymbolAddress((void**)&p_wtlo, g_wtlo);
    cudaGetSymbolAddress((void**)&p_wthi2, g_wthi2);
    cudaGetSymbolAddress((void**)&p_wtlo2, g_wtlo2);

    cudaFuncSetAttribute(k_wgemm, cudaFuncAttributeMaxDynamicSharedMemorySize, WG_SMEM);

    // side stream + fork/join events (created once, on the uncaptured first call;
    // captured graph is identical on every call)
    static cudaStream_t s2s = nullptr;
    static cudaEvent_t evFork = nullptr, evJoin = nullptr;
    if (!s2s) {
        cudaStreamCreateWithFlags(&s2s, cudaStreamNonBlocking);
        cudaEventCreateWithFlags(&evFork, cudaEventDisableTiming);
        cudaEventCreateWithFlags(&evJoin, cudaEventDisableTiming);
    }

    const int TB = 256;
    dim3 wg_grid(2, (NN + 127) / 128);
    dim3 gemm_grid_64(1, (NN + 63) / 64);
    int agg_blocks = (NN + 3) / 4;

    float* st0 = p_stats;
    float* st1 = p_stats + 512;
    float* st2 = p_stats + 1024;
    float* st3 = p_stats + 1536;

    // ---- fork: side chain (CSR build + stats zero + W2 transpose) ----
    cudaEventRecord(evFork, 0);
    cudaStreamWaitEvent(s2s, evFork, 0);
    k_zeroi<<<(NN + TB - 1) / TB, TB, 0, s2s>>>(p_cnt, NN);
    k_count<<<(EE + TB - 1) / TB, TB, 0, s2s>>>(ei, p_cnt);
    k_scan<<<1, 1024, 0, s2s>>>(p_cnt, p_rs, p_cur);
    k_scatter<<<(EE + TB - 1) / TB, TB, 0, s2s>>>(ei, p_cur, p_srcs);
    k_zerof<<<8, TB, 0, s2s>>>(p_stats, 2048);
    k_cvt_wt<<<(256 * 256 + TB - 1) / TB, TB, 0, s2s>>>(W2, p_wthi2, p_wtlo2, 256, 256);
    cudaEventRecord(evJoin, s2s);

    // ---- main chain: conv1 GEMM ----
    k_cvt<<<(NN * 128 + TB - 1) / TB, TB>>>(x, p_ahi, p_alo, NN * 128);
    k_cvt_wt<<<(128 * 256 + TB - 1) / TB, TB>>>(W1, p_wthi, p_wtlo, 128, 256);
    k_wgemm<<<wg_grid, TB, WG_SMEM>>>(p_ahi, p_alo, p_wthi, p_wtlo, p_h,
                                      a1_src, a1_dst, p_als, p_ald,
                                      NN, 128, 256);

    // ---- join, then conv1 softmax + aggregation ----
    cudaStreamWaitEvent(0, evJoin, 0);
    k_softmax<<<(NN * 32 + TB - 1) / TB, TB>>>(p_als, p_ald, p_rs, p_srcs, p_p, p_den);
    k_agg4<false><<<agg_blocks, TB>>>(p_h, p_p, p_den, p_rs, p_srcs, b1, p_agg);

    // ---- bn1 stats -> scale/shift (applied in conv2 A conversion) ----
    k_bnstats<<<(NN + 255) / 256, TB>>>(p_agg, st0, NN, 256, 256);
    k_bnprep<<<1, 256>>>(st0, bn1_g, bn1_b, p_scale, p_shift, NN, 256);

    // ---- conv2 ----
    k_cvt_bn<<<(NN * 256 + TB - 1) / TB, TB>>>(p_agg, p_scale, p_shift,
                                               p_ahi, p_alo, NN * 256);
    k_wgemm<<<wg_grid, TB, WG_SMEM>>>(p_ahi, p_alo, p_wthi2, p_wtlo2, p_h,
                                      a2_src, a2_dst, p_als, p_ald,
                                      NN, 256, 256);
    k_softmax<<<(NN * 32 + TB - 1) / TB, TB>>>(p_als, p_ald, p_rs, p_srcs, p_p, p_den);
    k_agg4<true><<<agg_blocks, TB>>>(p_h, p_p, p_den, p_rs, p_srcs, b2, p_s1);

    // ---- bn2 stats -> folded into lin1 (no relu) ----
    k_bnstats<<<(NN + 255) / 256, TB>>>(p_s1, st1, NN, 64, 256);
    k_gemm<<<gemm_grid_64, TB>>>(p_s1, lin1_W, lin1_b, p_s2, NN, 64, 64,
                                 st1, bn2_g, bn2_b, 0);

    // ---- bn3 stats -> folded into lin2 (relu) ----
    k_bnstats<<<(NN + 255) / 256, TB>>>(p_s2, st2, NN, 64, 256);
    k_gemm<<<gemm_grid_64, TB>>>(p_s2, lin2_W, lin2_b, p_s1, NN, 64, 64,
                                 st2, bn3_g, bn3_b, 1);

    // ---- bn4 stats -> fused bn4+relu+fin dot+sigmoid ----
    k_bnstats<<<(NN + 255) / 256, TB>>>(p_s1, st3, NN, 64, 256);
    k_bnfin<<<(NN + 7) / 8, TB>>>(p_s1, st3, bn4_g, bn4_b, fin_W, fin_b, out);
}

// round 15
// speedup vs baseline: 1.1914x; 1.1114x over previous
#include <cuda_runtime.h>
#include <cuda_bf16.h>
#include <cuda_fp16.h>
#include <mma.h>
#include <math.h>
#include <stdint.h>

using namespace nvcuda;

#define NN 50000
#define EE 800000
#define BN_EPS 1e-5f

// ---------------- scratch (static device globals; no runtime alloc) ----------------
__device__ __half g_h[NN * 256];     // conv GEMM output, fp16
__device__ float g_agg[NN * 256];
__device__ float g_s1[NN * 64];
__device__ float g_s2[NN * 64];
__device__ float g_als[NN * 4];
__device__ float g_ald[NN * 4];
__device__ float g_den[NN * 4];
__device__ float g_p[EE * 4];
__device__ int   g_cnt[NN];
__device__ int   g_rs[NN + 1];
__device__ int   g_cur[NN];
__device__ int   g_srcs[EE];
__device__ float g_stats[2048];
__device__ float g_scale[256];
__device__ float g_shift[256];
__device__ __nv_bfloat16 g_ahi[NN * 256];
__device__ __nv_bfloat16 g_alo[NN * 256];
__device__ __nv_bfloat16 g_wthi[256 * 256];
__device__ __nv_bfloat16 g_wtlo[256 * 256];
__device__ __nv_bfloat16 g_wthi2[256 * 256];
__device__ __nv_bfloat16 g_wtlo2[256 * 256];

// ---------------- tiny utility kernels ----------------
__global__ void k_zeroi(int* __restrict__ p, int n) {
    int i = blockIdx.x * blockDim.x + threadIdx.x;
    if (i < n) p[i] = 0;
}
__global__ void k_zerof(float* __restrict__ p, int n) {
    int i = blockIdx.x * blockDim.x + threadIdx.x;
    if (i < n) p[i] = 0.f;
}

// ---------------- fp32 -> bf16 hi/lo split conversions ----------------
__global__ void k_cvt(const float* __restrict__ a, __nv_bfloat16* __restrict__ hi,
                      __nv_bfloat16* __restrict__ lo, int total) {
    int i = blockIdx.x * blockDim.x + threadIdx.x;
    if (i >= total) return;
    float v = a[i];
    __nv_bfloat16 h = __float2bfloat16(v);
    hi[i] = h;
    lo[i] = __float2bfloat16(v - __bfloat162float(h));
}

__global__ void k_cvt_bn(const float* __restrict__ a, const float* __restrict__ sc,
                         const float* __restrict__ sh, __nv_bfloat16* __restrict__ hi,
                         __nv_bfloat16* __restrict__ lo, int total) {
    int i = blockIdx.x * blockDim.x + threadIdx.x;
    if (i >= total) return;
    int c = i & 255;
    float v = fmaxf(fmaf(a[i], sc[c], sh[c]), 0.f);
    __nv_bfloat16 h = __float2bfloat16(v);
    hi[i] = h;
    lo[i] = __float2bfloat16(v - __bfloat162float(h));
}

// W [K,cout] -> transposed Wt [cout,K] hi/lo bf16
__global__ void k_cvt_wt(const float* __restrict__ w, __nv_bfloat16* __restrict__ hi,
                         __nv_bfloat16* __restrict__ lo, int K, int cout) {
    int i = blockIdx.x * blockDim.x + threadIdx.x;
    if (i >= K * cout) return;
    int k = i / cout;
    int c = i - k * cout;
    float v = w[i];
    __nv_bfloat16 h = __float2bfloat16(v);
    hi[c * K + k] = h;
    lo[c * K + k] = __float2bfloat16(v - __bfloat162float(h));
}

// ---------------- CSR build ----------------
__global__ void k_count(const int* __restrict__ ei, int* __restrict__ cnt) {
    int e = blockIdx.x * blockDim.x + threadIdx.x;
    if (e < EE) atomicAdd(&cnt[ei[EE + e]], 1);
}

__global__ void k_scan(const int* __restrict__ cnt, int* __restrict__ rs,
                       int* __restrict__ cur) {
    __shared__ int sh[1024];
    int t = threadIdx.x;
    const int n = NN;
    int chunk = (n + 1023) >> 10;
    int b0 = t * chunk;
    int b1 = b0 + chunk; if (b1 > n) b1 = n; if (b0 > n) b0 = n;
    int local = 0;
    for (int i = b0; i < b1; i++) local += cnt[i];
    sh[t] = local;
    __syncthreads();
    for (int off = 1; off < 1024; off <<= 1) {
        int v = (t >= off) ? sh[t - off] : 0;
        __syncthreads();
        sh[t] += v;
        __syncthreads();
    }
    int base = sh[t] - local;
    for (int i = b0; i < b1; i++) { rs[i] = base; cur[i] = base; base += cnt[i]; }
    if (t == 1023) rs[n] = sh[1023];
}

__global__ void k_scatter(const int* __restrict__ ei, int* __restrict__ cur,
                          int* __restrict__ srcs) {
    int e = blockIdx.x * blockDim.x + threadIdx.x;
    if (e < EE) {
        int d = ei[EE + e];
        int pos = atomicAdd(&cur[d], 1);
        srcs[pos] = ei[e];
    }
}

// ================= WMMA bf16-split GEMM, cp.async double-buffered =================
// C written as fp16 (attention logits computed from fp32 accumulators).
#define WG_LD        40
#define WG_MAT       (128 * WG_LD)
#define WG_BUF       (4 * WG_MAT)
#define WG_BUF_BYTES (WG_BUF * 2)
#define WG_SMEM      (2 * WG_BUF_BYTES)

__device__ __forceinline__ void cp16(uint32_t dst, const void* src, int sz) {
    asm volatile("cp.async.ca.shared.global [%0], [%1], 16, %2;"
                 :: "r"(dst), "l"(src), "r"(sz));
}
__device__ __forceinline__ void cp_commit() {
    asm volatile("cp.async.commit_group;" ::: "memory");
}
template <int N>
__device__ __forceinline__ void cp_wait() {
    asm volatile("cp.async.wait_group %0;" :: "n"(N) : "memory");
}

__device__ __forceinline__ uint32_t h2_bits(__half2 h) {
    return *reinterpret_cast<const uint32_t*>(&h);
}

__global__ void __launch_bounds__(256, 2)
k_wgemm(const __nv_bfloat16* __restrict__ Ahi, const __nv_bfloat16* __restrict__ Alo,
        const __nv_bfloat16* __restrict__ Bhi, const __nv_bfloat16* __restrict__ Blo,
        __half* __restrict__ C, const float* __restrict__ asrc,
        const float* __restrict__ adst, float* __restrict__ als,
        float* __restrict__ ald, int n, int K, int cout) {
    extern __shared__ __align__(16) __nv_bfloat16 sm[];
    int tid = threadIdx.x;
    int wid = tid >> 5;
    int lane = tid & 31;
    int wm = wid >> 1;
    int wn = wid & 1;
    int row0 = blockIdx.y * 128;
    int col0 = blockIdx.x * 128;

    int r0i = tid >> 2,         c0i = (tid & 3) * 8;
    int r1i = (tid + 256) >> 2, c1i = (tid & 3) * 8;
    int gr0 = row0 + r0i, gr1 = row0 + r1i;
    int sza0 = (gr0 < n) ? 16 : 0;
    int sza1 = (gr1 < n) ? 16 : 0;
    int ar0 = (gr0 < n) ? gr0 : 0;
    int ar1 = (gr1 < n) ? gr1 : 0;

    uint32_t sbase = (uint32_t)__cvta_generic_to_shared(sm);
    uint32_t so0 = (uint32_t)((r0i * WG_LD + c0i) * 2);
    uint32_t so1 = (uint32_t)((r1i * WG_LD + c1i) * 2);
    const uint32_t MATB = WG_MAT * 2;

    int nch = K >> 5;

    auto issue = [&](int ch, int buf) {
        int k0 = ch << 5;
        uint32_t b = sbase + (uint32_t)buf * WG_BUF_BYTES;
        size_t a0 = (size_t)ar0 * K + k0 + c0i;
        size_t a1 = (size_t)ar1 * K + k0 + c1i;
        size_t b0 = (size_t)(col0 + r0i) * K + k0 + c0i;
        size_t b1 = (size_t)(col0 + r1i) * K + k0 + c1i;
        cp16(b + so0, &Ahi[a0], sza0);
        cp16(b + so1, &Ahi[a1], sza1);
        cp16(b + MATB + so0, &Alo[a0], sza0);
        cp16(b + MATB + so1, &Alo[a1], sza1);
        cp16(b + 2 * MATB + so0, &Bhi[b0], 16);
        cp16(b + 2 * MATB + so1, &Bhi[b1], 16);
        cp16(b + 3 * MATB + so0, &Blo[b0], 16);
        cp16(b + 3 * MATB + so1, &Blo[b1], 16);
    };

    issue(0, 0);
    cp_commit();

    wmma::fragment<wmma::accumulator, 16, 16, 16, float> acc[2][4];
#pragma unroll
    for (int i = 0; i < 2; i++)
#pragma unroll
        for (int j = 0; j < 4; j++) wmma::fill_fragment(acc[i][j], 0.f);

    for (int ch = 0; ch < nch; ch++) {
        if (ch + 1 < nch) {
            issue(ch + 1, (ch + 1) & 1);
            cp_commit();
            cp_wait<1>();
        } else {
            cp_wait<0>();
        }
        __syncthreads();
        int cur = (ch & 1) * WG_BUF;
#pragma unroll
        for (int ks = 0; ks < 2; ks++) {
            wmma::fragment<wmma::matrix_a, 16, 16, 16, __nv_bfloat16, wmma::row_major> ah[2], al[2];
            const __nv_bfloat16* pa = &sm[cur + (wm * 32) * WG_LD + ks * 16];
            wmma::load_matrix_sync(ah[0], pa, WG_LD);
            wmma::load_matrix_sync(ah[1], pa + 16 * WG_LD, WG_LD);
            wmma::load_matrix_sync(al[0], pa + WG_MAT, WG_LD);
            wmma::load_matrix_sync(al[1], pa + WG_MAT + 16 * WG_LD, WG_LD);
#pragma unroll
            for (int j = 0; j < 4; j++) {
                wmma::fragment<wmma::matrix_b, 16, 16, 16, __nv_bfloat16, wmma::col_major> bh, bl;
                const __nv_bfloat16* pb =
                    &sm[cur + 2 * WG_MAT + (wn * 64 + j * 16) * WG_LD + ks * 16];
                wmma::load_matrix_sync(bh, pb, WG_LD);
                wmma::load_matrix_sync(bl, pb + WG_MAT, WG_LD);
                wmma::mma_sync(acc[0][j], ah[0], bh, acc[0][j]);
                wmma::mma_sync(acc[0][j], ah[0], bl, acc[0][j]);
                wmma::mma_sync(acc[0][j], al[0], bh, acc[0][j]);
                wmma::mma_sync(acc[1][j], ah[1], bh, acc[1][j]);
                wmma::mma_sync(acc[1][j], ah[1], bl, acc[1][j]);
                wmma::mma_sync(acc[1][j], al[1], bh, acc[1][j]);
            }
        }
        __syncthreads();
    }

    // ---- epilogue: stage C tile in smem, write C (fp16) coalesced, compute als/ald
    float* smC = reinterpret_cast<float*>(sm);
    const int CLD = 132;
#pragma unroll
    for (int i = 0; i < 2; i++)
#pragma unroll
        for (int j = 0; j < 4; j++)
            wmma::store_matrix_sync(smC + (wm * 32 + i * 16) * CLD + wn * 64 + j * 16,
                                    acc[i][j], CLD, wmma::mem_row_major);
    __syncthreads();

    // fp16 C store: 128 rows x 128 cols = 2048 slots of 8 fp16 (16B)
    for (int t = tid; t < 128 * 16; t += 256) {
        int r = t >> 4, c8 = (t & 15) * 8;
        int gr = row0 + r;
        if (gr < n) {
            const float* p = &smC[r * CLD + c8];
            uint4 u;
            u.x = h2_bits(__floats2half2_rn(p[0], p[1]));
            u.y = h2_bits(__floats2half2_rn(p[2], p[3]));
            u.z = h2_bits(__floats2half2_rn(p[4], p[5]));
            u.w = h2_bits(__floats2half2_rn(p[6], p[7]));
            *reinterpret_cast<uint4*>(&C[(size_t)gr * cout + col0 + c8]) = u;
        }
    }

    int half = lane >> 4;
    int l16 = lane & 15;
    int head = blockIdx.x * 2 + half;
    float4 as4 = *reinterpret_cast<const float4*>(&asrc[head * 64 + l16 * 4]);
    float4 ad4 = *reinterpret_cast<const float4*>(&adst[head * 64 + l16 * 4]);
#pragma unroll
    for (int rr = 0; rr < 16; rr++) {
        int r = wid * 16 + rr;
        int gr = row0 + r;
        float4 v = *reinterpret_cast<const float4*>(&smC[r * CLD + half * 64 + l16 * 4]);
        float vs = v.x * as4.x + v.y * as4.y + v.z * as4.z + v.w * as4.w;
        float vd = v.x * ad4.x + v.y * ad4.y + v.z * ad4.z + v.w * ad4.w;
#pragma unroll
        for (int o = 8; o; o >>= 1) {
            vs += __shfl_xor_sync(0xffffffffu, vs, o);
            vd += __shfl_xor_sync(0xffffffffu, vd, o);
        }
        if (l16 == 0 && gr < n) {
            als[gr * 4 + head] = vs;
            ald[gr * 4 + head] = vd;
        }
    }
}

// ---------------- small GEMM (64-wide), fused bn prep (from stats) + relu on A ----
__global__ void k_gemm(const float* __restrict__ A, const float* __restrict__ W,
                       const float* __restrict__ bias, float* __restrict__ C,
                       int n, int K, int cout,
                       const float* __restrict__ stats, const float* __restrict__ bng,
                       const float* __restrict__ bnb, int dorelu) {
    __shared__ __align__(16) float As[16][68];
    __shared__ __align__(16) float Ws[16][64];
    __shared__ float ssc[64], ssh[64];
    int tid = threadIdx.x;
    int tx = tid & 15;
    int ty = tid >> 4;
    int row0 = blockIdx.y * 64;
    int col0 = blockIdx.x * 64;

    if (stats && tid < 64) {
        float invn = 1.f / (float)n;
        float mu = stats[tid] * invn;
        float var = stats[64 + tid] * invn - mu * mu;
        float sc = rsqrtf(var + BN_EPS) * bng[tid];
        ssc[tid] = sc;
        ssh[tid] = bnb[tid] - mu * sc;
    }
    __syncthreads();

    float acc[4][4] = {};
    for (int k0 = 0; k0 < K; k0 += 16) {
#pragma unroll
        for (int i = 0; i < 4; i++) {
            int idx = tid + i * 256;
            int kk = idx & 15;
            int m  = idx >> 4;
            int gr = row0 + m;
            float v = (gr < n) ? A[(size_t)gr * K + k0 + kk] : 0.f;
            if (stats) {
                v = fmaf(v, ssc[k0 + kk], ssh[k0 + kk]);
                if (dorelu) v = fmaxf(v, 0.f);
            }
            As[kk][m] = v;
        }
#pragma unroll
        for (int i = 0; i < 4; i++) {
            int idx = tid + i * 256;
            int col = idx & 63;
            int kk  = idx >> 6;
            Ws[kk][col] = W[(size_t)(k0 + kk) * cout + col0 + col];
        }
        __syncthreads();
#pragma unroll
        for (int kk = 0; kk < 16; kk++) {
            float4 ra = *reinterpret_cast<const float4*>(&As[kk][ty * 4]);
            float4 rb = *reinterpret_cast<const float4*>(&Ws[kk][tx * 4]);
            float a[4] = {ra.x, ra.y, ra.z, ra.w};
            float b[4] = {rb.x, rb.y, rb.z, rb.w};
#pragma unroll
            for (int i = 0; i < 4; i++)
#pragma unroll
                for (int j = 0; j < 4; j++)
                    acc[i][j] = fmaf(a[i], b[j], acc[i][j]);
        }
        __syncthreads();
    }
#pragma unroll
    for (int i = 0; i < 4; i++) {
        int gr = row0 + ty * 4 + i;
        if (gr >= n) continue;
#pragma unroll
        for (int j = 0; j < 4; j++) {
            int gc = col0 + tx * 4 + j;
            float v = acc[i][j];
            if (bias) v += bias[gc];
            C[(size_t)gr * cout + gc] = v;
        }
    }
}

// ---------------- single-pass softmax ----------------
__global__ void k_softmax(const float* __restrict__ als, const float* __restrict__ ald,
                          const int* __restrict__ rs, const int* __restrict__ srcs,
                          float* __restrict__ pbuf, float* __restrict__ den) {
    int node = (blockIdx.x * blockDim.x + threadIdx.x) >> 5;
    int lane = threadIdx.x & 31;
    if (node >= NN) return;
    int beg = rs[node], end = rs[node + 1];
    float ad0 = ald[node * 4 + 0], ad1 = ald[node * 4 + 1];
    float ad2 = ald[node * 4 + 2], ad3 = ald[node * 4 + 3];
    float d0 = 0.f, d1 = 0.f, d2 = 0.f, d3 = 0.f;
    for (int j = beg + lane; j < end; j += 32) {
        int s = srcs[j];
        float e0 = als[s * 4 + 0] + ad0; e0 = e0 > 0.f ? e0 : 0.2f * e0;
        float e1 = als[s * 4 + 1] + ad1; e1 = e1 > 0.f ? e1 : 0.2f * e1;
        float e2 = als[s * 4 + 2] + ad2; e2 = e2 > 0.f ? e2 : 0.2f * e2;
        float e3 = als[s * 4 + 3] + ad3; e3 = e3 > 0.f ? e3 : 0.2f * e3;
        float p0 = __expf(e0); float p1 = __expf(e1);
        float p2 = __expf(e2); float p3 = __expf(e3);
        pbuf[j * 4 + 0] = p0; pbuf[j * 4 + 1] = p1;
        pbuf[j * 4 + 2] = p2; pbuf[j * 4 + 3] = p3;
        d0 += p0; d1 += p1; d2 += p2; d3 += p3;
    }
#pragma unroll
    for (int o = 16; o; o >>= 1) {
        d0 += __shfl_xor_sync(0xffffffffu, d0, o);
        d1 += __shfl_xor_sync(0xffffffffu, d1, o);
        d2 += __shfl_xor_sync(0xffffffffu, d2, o);
        d3 += __shfl_xor_sync(0xffffffffu, d3, o);
    }
    if (lane == 0) {
        den[node * 4 + 0] = d0; den[node * 4 + 1] = d1;
        den[node * 4 + 2] = d2; den[node * 4 + 3] = d3;
    }
}

// ---------------- aggregation: 8 nodes/block, 32 threads/node, fp16 h gathers -----
// NN % 8 == 0 (50000 = 6250*8) -> every block fully populated.
template <bool MEAN>
__global__ void k_agg8(const __half* __restrict__ hbuf, const float* __restrict__ pbuf,
                       const float* __restrict__ den, const int* __restrict__ rs,
                       const int* __restrict__ srcs, const float* __restrict__ bias,
                       float* __restrict__ out) {
    int grp = threadIdx.x >> 5;         // 0..7
    int lt  = threadIdx.x & 31;         // channels 8lt..8lt+7
    int node = blockIdx.x * 8 + grp;
    __shared__ float sm[8][256];

    int h = lt >> 3;                    // head of this channel group
    int beg = rs[node], end = rs[node + 1];
    float acc[8] = {};
    int j = beg;
    for (; j + 3 < end; j += 4) {
        int s0 = srcs[j], s1 = srcs[j + 1], s2 = srcs[j + 2], s3 = srcs[j + 3];
        float p0 = pbuf[j * 4 + h];
        float p1 = pbuf[(j + 1) * 4 + h];
        float p2 = pbuf[(j + 2) * 4 + h];
        float p3 = pbuf[(j + 3) * 4 + h];
        uint4 u0 = *reinterpret_cast<const uint4*>(&hbuf[(size_t)s0 * 256 + lt * 8]);
        uint4 u1 = *reinterpret_cast<const uint4*>(&hbuf[(size_t)s1 * 256 + lt * 8]);
        uint4 u2 = *reinterpret_cast<const uint4*>(&hbuf[(size_t)s2 * 256 + lt * 8]);
        uint4 u3 = *reinterpret_cast<const uint4*>(&hbuf[(size_t)s3 * 256 + lt * 8]);
#pragma unroll
        for (int q = 0; q < 4; q++) {
            float2 f0 = __half22float2(*reinterpret_cast<const __half2*>(&(&u0.x)[q]));
            float2 f1 = __half22float2(*reinterpret_cast<const __half2*>(&(&u1.x)[q]));
            float2 f2 = __half22float2(*reinterpret_cast<const __half2*>(&(&u2.x)[q]));
            float2 f3 = __half22float2(*reinterpret_cast<const __half2*>(&(&u3.x)[q]));
            acc[2 * q + 0] = fmaf(f0.x, p0, fmaf(f1.x, p1, fmaf(f2.x, p2, fmaf(f3.x, p3, acc[2 * q + 0]))));
            acc[2 * q + 1] = fmaf(f0.y, p0, fmaf(f1.y, p1, fmaf(f2.y, p2, fmaf(f3.y, p3, acc[2 * q + 1]))));
        }
    }
    for (; j < end; j++) {
        int s0 = srcs[j];
        float p0 = pbuf[j * 4 + h];
        uint4 u0 = *reinterpret_cast<const uint4*>(&hbuf[(size_t)s0 * 256 + lt * 8]);
#pragma unroll
        for (int q = 0; q < 4; q++) {
            float2 f0 = __half22float2(*reinterpret_cast<const __half2*>(&(&u0.x)[q]));
            acc[2 * q + 0] = fmaf(f0.x, p0, acc[2 * q + 0]);
            acc[2 * q + 1] = fmaf(f0.y, p0, acc[2 * q + 1]);
        }
    }
    float inv = 1.f / (den[node * 4 + h] + 1e-16f);
#pragma unroll
    for (int q = 0; q < 8; q++) acc[q] *= inv;

    if (!MEAN) {
        float4 b0 = *reinterpret_cast<const float4*>(&bias[lt * 8]);
        float4 b1 = *reinterpret_cast<const float4*>(&bias[lt * 8 + 4]);
        float4 o0 = make_float4(acc[0] + b0.x, acc[1] + b0.y, acc[2] + b0.z, acc[3] + b0.w);
        float4 o1 = make_float4(acc[4] + b1.x, acc[5] + b1.y, acc[6] + b1.z, acc[7] + b1.w);
        *reinterpret_cast<float4*>(&out[(size_t)node * 256 + lt * 8]) = o0;
        *reinterpret_cast<float4*>(&out[(size_t)node * 256 + lt * 8 + 4]) = o1;
    } else {
#pragma unroll
        for (int q = 0; q < 8; q++) sm[grp][lt * 8 + q] = acc[q];
        __syncthreads();
        if (lt < 8) {
            float* row = sm[grp];
            int c = lt * 8;
            float4 o0, o1;
            o0.x = (row[c + 0] + row[c + 64] + row[c + 128] + row[c + 192]) * 0.25f + bias[c + 0];
            o0.y = (row[c + 1] + row[c + 65] + row[c + 129] + row[c + 193]) * 0.25f + bias[c + 1];
            o0.z = (row[c + 2] + row[c + 66] + row[c + 130] + row[c + 194]) * 0.25f + bias[c + 2];
            o0.w = (row[c + 3] + row[c + 67] + row[c + 131] + row[c + 195]) * 0.25f + bias[c + 3];
            o1.x = (row[c + 4] + row[c + 68] + row[c + 132] + row[c + 196]) * 0.25f + bias[c + 4];
            o1.y = (row[c + 5] + row[c + 69] + row[c + 133] + row[c + 197]) * 0.25f + bias[c + 5];
            o1.z = (row[c + 6] + row[c + 70] + row[c + 134] + row[c + 198]) * 0.25f + bias[c + 6];
            o1.w = (row[c + 7] + row[c + 71] + row[c + 135] + row[c + 199]) * 0.25f + bias[c + 7];
            *reinterpret_cast<float4*>(&out[(size_t)node * 64 + c]) = o0;
            *reinterpret_cast<float4*>(&out[(size_t)node * 64 + c + 4]) = o1;
        }
    }
}

// ---------------- batchnorm stats ----------------
__global__ void k_bnstats(const float* __restrict__ x, float* __restrict__ stats,
                          int n, int C, int rowsPerBlk) {
    int c = threadIdx.x % C;
    int rl = threadIdx.x / C;
    int lanes = blockDim.x / C;
    int r0 = blockIdx.x * rowsPerBlk;
    int r1 = r0 + rowsPerBlk; if (r1 > n) r1 = n;
    float s = 0.f, s2 = 0.f;
    for (int r = r0 + rl; r < r1; r += lanes) {
        float v = x[(size_t)r * C + c];
        s += v; s2 += v * v;
    }
    __shared__ float sh[2][256];
    sh[0][threadIdx.x] = s; sh[1][threadIdx.x] = s2;
    __syncthreads();
    if (rl == 0) {
        for (int l = 1; l < lanes; l++) {
            s += sh[0][c + l * C]; s2 += sh[1][c + l * C];
        }
        atomicAdd(&stats[c], s);
        atomicAdd(&stats[C + c], s2);
    }
}

__global__ void k_bnprep(const float* __restrict__ stats, const float* __restrict__ g,
                         const float* __restrict__ b, float* __restrict__ scale,
                         float* __restrict__ shift, int n, int C) {
    int c = threadIdx.x + blockIdx.x * blockDim.x;
    if (c >= C) return;
    float invn = 1.f / (float)n;
    float mu = stats[c] * invn;
    float var = stats[C + c] * invn - mu * mu;
    float sc = rsqrtf(var + BN_EPS) * g[c];
    scale[c] = sc;
    shift[c] = b[c] - mu * sc;
}

// ---------------- fused bn4 + relu + final dot + sigmoid ----------------
__global__ void k_bnfin(const float* __restrict__ x, const float* __restrict__ stats,
                        const float* __restrict__ g, const float* __restrict__ b,
                        const float* __restrict__ w, const float* __restrict__ fb,
                        float* __restrict__ out) {
    int row = blockIdx.x * 8 + (threadIdx.x >> 5);
    int lane = threadIdx.x & 31;
    if (row >= NN) return;
    float invn = 1.f / (float)NN;
    float s = 0.f;
#pragma unroll
    for (int half = 0; half < 2; half++) {
        int c = lane + half * 32;
        float mu = stats[c] * invn;
        float var = stats[64 + c] * invn - mu * mu;
        float v = (x[(size_t)row * 64 + c] - mu) * rsqrtf(var + BN_EPS) * g[c] + b[c];
        v = fmaxf(v, 0.f);
        s = fmaf(v, w[c], s);
    }
#pragma unroll
    for (int o = 16; o; o >>= 1) s += __shfl_xor_sync(0xffffffffu, s, o);
    if (lane == 0) out[row] = 1.f / (1.f + __expf(-(s + fb[0])));
}

// ---------------- host launch ----------------
extern "C" void kernel_launch(void* const* d_in, const int* in_sizes, int n_in,
                              void* d_out, int out_size) {
    const float* x        = (const float*)d_in[0];
    const int*   ei       = (const int*)d_in[1];
    const float* W1       = (const float*)d_in[2];
    const float* a1_src   = (const float*)d_in[3];
    const float* a1_dst   = (const float*)d_in[4];
    const float* b1       = (const float*)d_in[5];
    const float* W2       = (const float*)d_in[6];
    const float* a2_src   = (const float*)d_in[7];
    const float* a2_dst   = (const float*)d_in[8];
    const float* b2       = (const float*)d_in[9];
    const float* bn1_g    = (const float*)d_in[10];
    const float* bn1_b    = (const float*)d_in[11];
    const float* bn2_g    = (const float*)d_in[12];
    const float* bn2_b    = (const float*)d_in[13];
    const float* bn3_g    = (const float*)d_in[14];
    const float* bn3_b    = (const float*)d_in[15];
    const float* bn4_g    = (const float*)d_in[16];
    const float* bn4_b    = (const float*)d_in[17];
    const float* lin1_W   = (const float*)d_in[18];
    const float* lin1_b   = (const float*)d_in[19];
    const float* lin2_W   = (const float*)d_in[20];
    const float* lin2_b   = (const float*)d_in[21];
    const float* fin_W    = (const float*)d_in[22];
    const float* fin_b    = (const float*)d_in[23];
    float* out            = (float*)d_out;

    float *p_agg, *p_s1, *p_s2, *p_als, *p_ald, *p_den, *p_p, *p_stats;
    float *p_scale, *p_shift;
    int *p_cnt, *p_rs, *p_cur, *p_srcs;
    __half *p_h;
    __nv_bfloat16 *p_ahi, *p_alo, *p_wthi, *p_wtlo, *p_wthi2, *p_wtlo2;
    cudaGetSymbolAddress((void**)&p_h, g_h);
    cudaGetSymbolAddress((void**)&p_agg, g_agg);
    cudaGetSymbolAddress((void**)&p_s1, g_s1);
    cudaGetSymbolAddress((void**)&p_s2, g_s2);
    cudaGetSymbolAddress((void**)&p_als, g_als);
    cudaGetSymbolAddress((void**)&p_ald, g_ald);
    cudaGetSymbolAddress((void**)&p_den, g_den);
    cudaGetSymbolAddress((void**)&p_p, g_p);
    cudaGetSymbolAddress((void**)&p_stats, g_stats);
    cudaGetSymbolAddress((void**)&p_scale, g_scale);
    cudaGetSymbolAddress((void**)&p_shift, g_shift);
    cudaGetSymbolAddress((void**)&p_cnt, g_cnt);
    cudaGetSymbolAddress((void**)&p_rs, g_rs);
    cudaGetSymbolAddress((void**)&p_cur, g_cur);
    cudaGetSymbolAddress((void**)&p_srcs, g_srcs);
    cudaGetSymbolAddress((void**)&p_ahi, g_ahi);
    cudaGetSymbolAddress((void**)&p_alo, g_alo);
    cudaGetSymbolAddress((void**)&p_wthi, g_wthi);
    cudaGetSymbolAddress((void**)&p_wtlo, g_wtlo);
    cudaGetSymbolAddress((void**)&p_wthi2, g_wthi2);
    cudaGetSymbolAddress((void**)&p_wtlo2, g_wtlo2);

    cudaFuncSetAttribute(k_wgemm, cudaFuncAttributeMaxDynamicSharedMemorySize, WG_SMEM);

    static cudaStream_t s2s = nullptr;
    static cudaEvent_t evFork = nullptr, evJoin = nullptr;
    if (!s2s) {
        cudaStreamCreateWithFlags(&s2s, cudaStreamNonBlocking);
        cudaEventCreateWithFlags(&evFork, cudaEventDisableTiming);
        cudaEventCreateWithFlags(&evJoin, cudaEventDisableTiming);
    }

    const int TB = 256;
    dim3 wg_grid(2, (NN + 127) / 128);
    dim3 gemm_grid_64(1, (NN + 63) / 64);
    int agg_blocks = NN / 8;     // 50000 % 8 == 0

    float* st0 = p_stats;
    float* st1 = p_stats + 512;
    float* st2 = p_stats + 1024;
    float* st3 = p_stats + 1536;

    // ---- fork: side chain (CSR build + stats zero + W2 transpose) ----
    cudaEventRecord(evFork, 0);
    cudaStreamWaitEvent(s2s, evFork, 0);
    k_zeroi<<<(NN + TB - 1) / TB, TB, 0, s2s>>>(p_cnt, NN);
    k_count<<<(EE + TB - 1) / TB, TB, 0, s2s>>>(ei, p_cnt);
    k_scan<<<1, 1024, 0, s2s>>>(p_cnt, p_rs, p_cur);
    k_scatter<<<(EE + TB - 1) / TB, TB, 0, s2s>>>(ei, p_cur, p_srcs);
    k_zerof<<<8, TB, 0, s2s>>>(p_stats, 2048);
    k_cvt_wt<<<(256 * 256 + TB - 1) / TB, TB, 0, s2s>>>(W2, p_wthi2, p_wtlo2, 256, 256);
    cudaEventRecord(evJoin, s2s);

    // ---- main chain: conv1 GEMM ----
    k_cvt<<<(NN * 128 + TB - 1) / TB, TB>>>(x, p_ahi, p_alo, NN * 128);
    k_cvt_wt<<<(128 * 256 + TB - 1) / TB, TB>>>(W1, p_wthi, p_wtlo, 128, 256);
    k_wgemm<<<wg_grid, TB, WG_SMEM>>>(p_ahi, p_alo, p_wthi, p_wtlo, p_h,
                                      a1_src, a1_dst, p_als, p_ald,
                                      NN, 128, 256);

    // ---- join, then conv1 softmax + aggregation ----
    cudaStreamWaitEvent(0, evJoin, 0);
    k_softmax<<<(NN * 32 + TB - 1) / TB, TB>>>(p_als, p_ald, p_rs, p_srcs, p_p, p_den);
    k_agg8<false><<<agg_blocks, TB>>>(p_h, p_p, p_den, p_rs, p_srcs, b1, p_agg);

    // ---- bn1 stats -> scale/shift (applied in conv2 A conversion) ----
    k_bnstats<<<(NN + 255) / 256, TB>>>(p_agg, st0, NN, 256, 256);
    k_bnprep<<<1, 256>>>(st0, bn1_g, bn1_b, p_scale, p_shift, NN, 256);

    // ---- conv2 ----
    k_cvt_bn<<<(NN * 256 + TB - 1) / TB, TB>>>(p_agg, p_scale, p_shift,
                                               p_ahi, p_alo, NN * 256);
    k_wgemm<<<wg_grid, TB, WG_SMEM>>>(p_ahi, p_alo, p_wthi2, p_wtlo2, p_h,
                                      a2_src, a2_dst, p_als, p_ald,
                                      NN, 256, 256);
    k_softmax<<<(NN * 32 + TB - 1) / TB, TB>>>(p_als, p_ald, p_rs, p_srcs, p_p, p_den);
    k_agg8<true><<<agg_blocks, TB>>>(p_h, p_p, p_den, p_rs, p_srcs, b2, p_s1);

    // ---- bn2 stats -> folded into lin1 (no relu) ----
    k_bnstats<<<(NN + 255) / 256, TB>>>(p_s1, st1, NN, 64, 256);
    k_gemm<<<gemm_grid_64, TB>>>(p_s1, lin1_W, lin1_b, p_s2, NN, 64, 64,
                                 st1, bn2_g, bn2_b, 0);

    // ---- bn3 stats -> folded into lin2 (relu) ----
    k_bnstats<<<(NN + 255) / 256, TB>>>(p_s2, st2, NN, 64, 256);
    k_gemm<<<gemm_grid_64, TB>>>(p_s2, lin2_W, lin2_b, p_s1, NN, 64, 64,
                                 st2, bn3_g, bn3_b, 1);

    // ---- bn4 stats -> fused bn4+relu+fin dot+sigmoid ----
    k_bnstats<<<(NN + 255) / 256, TB>>>(p_s1, st3, NN, 64, 256);
    k_bnfin<<<(NN + 7) / 8, TB>>>(p_s1, st3, bn4_g, bn4_b, fin_W, fin_b, out);
}

// round 16
// speedup vs baseline: 1.1923x; 1.0008x over previous
#include <cuda_runtime.h>
#include <cuda_bf16.h>
#include <cuda_fp16.h>
#include <mma.h>
#include <math.h>
#include <stdint.h>

using namespace nvcuda;

#define NN 50000
#define EE 800000
#define BN_EPS 1e-5f

// ---------------- scratch (static device globals; no runtime alloc) ----------------
__device__ __half g_h[NN * 256];     // conv GEMM output, fp16
__device__ float g_agg[NN * 256];
__device__ float g_s1[NN * 64];
__device__ float g_s2[NN * 64];
__device__ float g_als[NN * 4];
__device__ float g_ald[NN * 4];
__device__ int   g_cnt[NN];
__device__ int   g_rs[NN + 1];
__device__ int   g_cur[NN];
__device__ int   g_srcs[EE];
__device__ float g_stats[2048];
__device__ float g_scale[256];
__device__ float g_shift[256];
__device__ __nv_bfloat16 g_ahi[NN * 256];
__device__ __nv_bfloat16 g_alo[NN * 256];
__device__ __nv_bfloat16 g_wthi[256 * 256];
__device__ __nv_bfloat16 g_wtlo[256 * 256];
__device__ __nv_bfloat16 g_wthi2[256 * 256];
__device__ __nv_bfloat16 g_wtlo2[256 * 256];

// ---------------- tiny utility kernels ----------------
__global__ void k_zeroi(int* __restrict__ p, int n) {
    int i = blockIdx.x * blockDim.x + threadIdx.x;
    if (i < n) p[i] = 0;
}
__global__ void k_zerof(float* __restrict__ p, int n) {
    int i = blockIdx.x * blockDim.x + threadIdx.x;
    if (i < n) p[i] = 0.f;
}

// ---------------- fp32 -> bf16 hi/lo split conversions ----------------
__global__ void k_cvt(const float* __restrict__ a, __nv_bfloat16* __restrict__ hi,
                      __nv_bfloat16* __restrict__ lo, int total) {
    int i = blockIdx.x * blockDim.x + threadIdx.x;
    if (i >= total) return;
    float v = a[i];
    __nv_bfloat16 h = __float2bfloat16(v);
    hi[i] = h;
    lo[i] = __float2bfloat16(v - __bfloat162float(h));
}

__global__ void k_cvt_bn(const float* __restrict__ a, const float* __restrict__ sc,
                         const float* __restrict__ sh, __nv_bfloat16* __restrict__ hi,
                         __nv_bfloat16* __restrict__ lo, int total) {
    int i = blockIdx.x * blockDim.x + threadIdx.x;
    if (i >= total) return;
    int c = i & 255;
    float v = fmaxf(fmaf(a[i], sc[c], sh[c]), 0.f);
    __nv_bfloat16 h = __float2bfloat16(v);
    hi[i] = h;
    lo[i] = __float2bfloat16(v - __bfloat162float(h));
}

// W [K,cout] -> transposed Wt [cout,K] hi/lo bf16
__global__ void k_cvt_wt(const float* __restrict__ w, __nv_bfloat16* __restrict__ hi,
                         __nv_bfloat16* __restrict__ lo, int K, int cout) {
    int i = blockIdx.x * blockDim.x + threadIdx.x;
    if (i >= K * cout) return;
    int k = i / cout;
    int c = i - k * cout;
    float v = w[i];
    __nv_bfloat16 h = __float2bfloat16(v);
    hi[c * K + k] = h;
    lo[c * K + k] = __float2bfloat16(v - __bfloat162float(h));
}

// ---------------- CSR build ----------------
__global__ void k_count(const int* __restrict__ ei, int* __restrict__ cnt) {
    int e = blockIdx.x * blockDim.x + threadIdx.x;
    if (e < EE) atomicAdd(&cnt[ei[EE + e]], 1);
}

__global__ void k_scan(const int* __restrict__ cnt, int* __restrict__ rs,
                       int* __restrict__ cur) {
    __shared__ int sh[1024];
    int t = threadIdx.x;
    const int n = NN;
    int chunk = (n + 1023) >> 10;
    int b0 = t * chunk;
    int b1 = b0 + chunk; if (b1 > n) b1 = n; if (b0 > n) b0 = n;
    int local = 0;
    for (int i = b0; i < b1; i++) local += cnt[i];
    sh[t] = local;
    __syncthreads();
    for (int off = 1; off < 1024; off <<= 1) {
        int v = (t >= off) ? sh[t - off] : 0;
        __syncthreads();
        sh[t] += v;
        __syncthreads();
    }
    int base = sh[t] - local;
    for (int i = b0; i < b1; i++) { rs[i] = base; cur[i] = base; base += cnt[i]; }
    if (t == 1023) rs[n] = sh[1023];
}

__global__ void k_scatter(const int* __restrict__ ei, int* __restrict__ cur,
                          int* __restrict__ srcs) {
    int e = blockIdx.x * blockDim.x + threadIdx.x;
    if (e < EE) {
        int d = ei[EE + e];
        int pos = atomicAdd(&cur[d], 1);
        srcs[pos] = ei[e];
    }
}

// ================= WMMA bf16-split GEMM, cp.async double-buffered =================
#define WG_LD        40
#define WG_MAT       (128 * WG_LD)
#define WG_BUF       (4 * WG_MAT)
#define WG_BUF_BYTES (WG_BUF * 2)
#define WG_SMEM      (2 * WG_BUF_BYTES)

__device__ __forceinline__ void cp16(uint32_t dst, const void* src, int sz) {
    asm volatile("cp.async.ca.shared.global [%0], [%1], 16, %2;"
                 :: "r"(dst), "l"(src), "r"(sz));
}
__device__ __forceinline__ void cp_commit() {
    asm volatile("cp.async.commit_group;" ::: "memory");
}
template <int N>
__device__ __forceinline__ void cp_wait() {
    asm volatile("cp.async.wait_group %0;" :: "n"(N) : "memory");
}

__device__ __forceinline__ uint32_t h2_bits(__half2 h) {
    return *reinterpret_cast<const uint32_t*>(&h);
}

__global__ void __launch_bounds__(256, 2)
k_wgemm(const __nv_bfloat16* __restrict__ Ahi, const __nv_bfloat16* __restrict__ Alo,
        const __nv_bfloat16* __restrict__ Bhi, const __nv_bfloat16* __restrict__ Blo,
        __half* __restrict__ C, const float* __restrict__ asrc,
        const float* __restrict__ adst, float* __restrict__ als,
        float* __restrict__ ald, int n, int K, int cout) {
    extern __shared__ __align__(16) __nv_bfloat16 sm[];
    int tid = threadIdx.x;
    int wid = tid >> 5;
    int lane = tid & 31;
    int wm = wid >> 1;
    int wn = wid & 1;
    int row0 = blockIdx.y * 128;
    int col0 = blockIdx.x * 128;

    int r0i = tid >> 2,         c0i = (tid & 3) * 8;
    int r1i = (tid + 256) >> 2, c1i = (tid & 3) * 8;
    int gr0 = row0 + r0i, gr1 = row0 + r1i;
    int sza0 = (gr0 < n) ? 16 : 0;
    int sza1 = (gr1 < n) ? 16 : 0;
    int ar0 = (gr0 < n) ? gr0 : 0;
    int ar1 = (gr1 < n) ? gr1 : 0;

    uint32_t sbase = (uint32_t)__cvta_generic_to_shared(sm);
    uint32_t so0 = (uint32_t)((r0i * WG_LD + c0i) * 2);
    uint32_t so1 = (uint32_t)((r1i * WG_LD + c1i) * 2);
    const uint32_t MATB = WG_MAT * 2;

    int nch = K >> 5;

    auto issue = [&](int ch, int buf) {
        int k0 = ch << 5;
        uint32_t b = sbase + (uint32_t)buf * WG_BUF_BYTES;
        size_t a0 = (size_t)ar0 * K + k0 + c0i;
        size_t a1 = (size_t)ar1 * K + k0 + c1i;
        size_t b0 = (size_t)(col0 + r0i) * K + k0 + c0i;
        size_t b1 = (size_t)(col0 + r1i) * K + k0 + c1i;
        cp16(b + so0, &Ahi[a0], sza0);
        cp16(b + so1, &Ahi[a1], sza1);
        cp16(b + MATB + so0, &Alo[a0], sza0);
        cp16(b + MATB + so1, &Alo[a1], sza1);
        cp16(b + 2 * MATB + so0, &Bhi[b0], 16);
        cp16(b + 2 * MATB + so1, &Bhi[b1], 16);
        cp16(b + 3 * MATB + so0, &Blo[b0], 16);
        cp16(b + 3 * MATB + so1, &Blo[b1], 16);
    };

    issue(0, 0);
    cp_commit();

    wmma::fragment<wmma::accumulator, 16, 16, 16, float> acc[2][4];
#pragma unroll
    for (int i = 0; i < 2; i++)
#pragma unroll
        for (int j = 0; j < 4; j++) wmma::fill_fragment(acc[i][j], 0.f);

    for (int ch = 0; ch < nch; ch++) {
        if (ch + 1 < nch) {
            issue(ch + 1, (ch + 1) & 1);
            cp_commit();
            cp_wait<1>();
        } else {
            cp_wait<0>();
        }
        __syncthreads();
        int cur = (ch & 1) * WG_BUF;
#pragma unroll
        for (int ks = 0; ks < 2; ks++) {
            wmma::fragment<wmma::matrix_a, 16, 16, 16, __nv_bfloat16, wmma::row_major> ah[2], al[2];
            const __nv_bfloat16* pa = &sm[cur + (wm * 32) * WG_LD + ks * 16];
            wmma::load_matrix_sync(ah[0], pa, WG_LD);
            wmma::load_matrix_sync(ah[1], pa + 16 * WG_LD, WG_LD);
            wmma::load_matrix_sync(al[0], pa + WG_MAT, WG_LD);
            wmma::load_matrix_sync(al[1], pa + WG_MAT + 16 * WG_LD, WG_LD);
#pragma unroll
            for (int j = 0; j < 4; j++) {
                wmma::fragment<wmma::matrix_b, 16, 16, 16, __nv_bfloat16, wmma::col_major> bh, bl;
                const __nv_bfloat16* pb =
                    &sm[cur + 2 * WG_MAT + (wn * 64 + j * 16) * WG_LD + ks * 16];
                wmma::load_matrix_sync(bh, pb, WG_LD);
                wmma::load_matrix_sync(bl, pb + WG_MAT, WG_LD);
                wmma::mma_sync(acc[0][j], ah[0], bh, acc[0][j]);
                wmma::mma_sync(acc[0][j], ah[0], bl, acc[0][j]);
                wmma::mma_sync(acc[0][j], al[0], bh, acc[0][j]);
                wmma::mma_sync(acc[1][j], ah[1], bh, acc[1][j]);
                wmma::mma_sync(acc[1][j], ah[1], bl, acc[1][j]);
                wmma::mma_sync(acc[1][j], al[1], bh, acc[1][j]);
            }
        }
        __syncthreads();
    }

    // ---- epilogue: stage C tile in smem, write C (fp16) coalesced, compute als/ald
    float* smC = reinterpret_cast<float*>(sm);
    const int CLD = 132;
#pragma unroll
    for (int i = 0; i < 2; i++)
#pragma unroll
        for (int j = 0; j < 4; j++)
            wmma::store_matrix_sync(smC + (wm * 32 + i * 16) * CLD + wn * 64 + j * 16,
                                    acc[i][j], CLD, wmma::mem_row_major);
    __syncthreads();

    for (int t = tid; t < 128 * 16; t += 256) {
        int r = t >> 4, c8 = (t & 15) * 8;
        int gr = row0 + r;
        if (gr < n) {
            const float* p = &smC[r * CLD + c8];
            uint4 u;
            u.x = h2_bits(__floats2half2_rn(p[0], p[1]));
            u.y = h2_bits(__floats2half2_rn(p[2], p[3]));
            u.z = h2_bits(__floats2half2_rn(p[4], p[5]));
            u.w = h2_bits(__floats2half2_rn(p[6], p[7]));
            *reinterpret_cast<uint4*>(&C[(size_t)gr * cout + col0 + c8]) = u;
        }
    }

    int half = lane >> 4;
    int l16 = lane & 15;
    int head = blockIdx.x * 2 + half;
    float4 as4 = *reinterpret_cast<const float4*>(&asrc[head * 64 + l16 * 4]);
    float4 ad4 = *reinterpret_cast<const float4*>(&adst[head * 64 + l16 * 4]);
#pragma unroll
    for (int rr = 0; rr < 16; rr++) {
        int r = wid * 16 + rr;
        int gr = row0 + r;
        float4 v = *reinterpret_cast<const float4*>(&smC[r * CLD + half * 64 + l16 * 4]);
        float vs = v.x * as4.x + v.y * as4.y + v.z * as4.z + v.w * as4.w;
        float vd = v.x * ad4.x + v.y * ad4.y + v.z * ad4.z + v.w * ad4.w;
#pragma unroll
        for (int o = 8; o; o >>= 1) {
            vs += __shfl_xor_sync(0xffffffffu, vs, o);
            vd += __shfl_xor_sync(0xffffffffu, vd, o);
        }
        if (l16 == 0 && gr < n) {
            als[gr * 4 + head] = vs;
            ald[gr * 4 + head] = vd;
        }
    }
}

// ---------------- small GEMM (64-wide), fused bn prep (from stats) + relu on A ----
__global__ void k_gemm(const float* __restrict__ A, const float* __restrict__ W,
                       const float* __restrict__ bias, float* __restrict__ C,
                       int n, int K, int cout,
                       const float* __restrict__ stats, const float* __restrict__ bng,
                       const float* __restrict__ bnb, int dorelu) {
    __shared__ __align__(16) float As[16][68];
    __shared__ __align__(16) float Ws[16][64];
    __shared__ float ssc[64], ssh[64];
    int tid = threadIdx.x;
    int tx = tid & 15;
    int ty = tid >> 4;
    int row0 = blockIdx.y * 64;
    int col0 = blockIdx.x * 64;

    if (stats && tid < 64) {
        float invn = 1.f / (float)n;
        float mu = stats[tid] * invn;
        float var = stats[64 + tid] * invn - mu * mu;
        float sc = rsqrtf(var + BN_EPS) * bng[tid];
        ssc[tid] = sc;
        ssh[tid] = bnb[tid] - mu * sc;
    }
    __syncthreads();

    float acc[4][4] = {};
    for (int k0 = 0; k0 < K; k0 += 16) {
#pragma unroll
        for (int i = 0; i < 4; i++) {
            int idx = tid + i * 256;
            int kk = idx & 15;
            int m  = idx >> 4;
            int gr = row0 + m;
            float v = (gr < n) ? A[(size_t)gr * K + k0 + kk] : 0.f;
            if (stats) {
                v = fmaf(v, ssc[k0 + kk], ssh[k0 + kk]);
                if (dorelu) v = fmaxf(v, 0.f);
            }
            As[kk][m] = v;
        }
#pragma unroll
        for (int i = 0; i < 4; i++) {
            int idx = tid + i * 256;
            int col = idx & 63;
            int kk  = idx >> 6;
            Ws[kk][col] = W[(size_t)(k0 + kk) * cout + col0 + col];
        }
        __syncthreads();
#pragma unroll
        for (int kk = 0; kk < 16; kk++) {
            float4 ra = *reinterpret_cast<const float4*>(&As[kk][ty * 4]);
            float4 rb = *reinterpret_cast<const float4*>(&Ws[kk][tx * 4]);
            float a[4] = {ra.x, ra.y, ra.z, ra.w};
            float b[4] = {rb.x, rb.y, rb.z, rb.w};
#pragma unroll
            for (int i = 0; i < 4; i++)
#pragma unroll
                for (int j = 0; j < 4; j++)
                    acc[i][j] = fmaf(a[i], b[j], acc[i][j]);
        }
        __syncthreads();
    }
#pragma unroll
    for (int i = 0; i < 4; i++) {
        int gr = row0 + ty * 4 + i;
        if (gr >= n) continue;
#pragma unroll
        for (int j = 0; j < 4; j++) {
            int gc = col0 + tx * 4 + j;
            float v = acc[i][j];
            if (bias) v += bias[gc];
            C[(size_t)gr * cout + gc] = v;
        }
    }
}

// ---- fused softmax + aggregation: 8 nodes/block, one WARP per node, shfl p-share --
// lane = h*8 + e (h = head 0..3, e = edge-slot 0..7). Each 8-edge chunk:
// lane computes p for edge j+e with head h, shfl-broadcasts (p, src) to the
// 8 lanes of head h, gathers fp16 h rows, accumulates den locally. No syncs.
template <bool MEAN>
__global__ void k_agg8f(const __half* __restrict__ hbuf, const float* __restrict__ als,
                        const float* __restrict__ ald, const int* __restrict__ rs,
                        const int* __restrict__ srcs, const float* __restrict__ bias,
                        float* __restrict__ out) {
    int grp = threadIdx.x >> 5;         // 0..7, one warp per node
    int lt  = threadIdx.x & 31;
    int node = blockIdx.x * 8 + grp;
    __shared__ float sm[8][256];

    int h = lt >> 3;                    // this lane's head (channels lt*8..lt*8+7)
    int el = lt & 7;                    // edge slot within chunk
    int srcLaneBase = lt & 24;          // = h*8
    int beg = rs[node], end = rs[node + 1];
    float aldh = ald[node * 4 + h];

    float acc[8] = {};
    float den = 0.f;

    for (int j = beg; j < end; j += 8) {
        int je = j + el;
        float p_mine = 0.f;
        int s_mine = 0;
        if (je < end) {
            s_mine = srcs[je];
            float e = als[s_mine * 4 + h] + aldh;
            e = e > 0.f ? e : 0.2f * e;
            p_mine = __expf(e);
        }
        int cnt = end - j; if (cnt > 8) cnt = 8;
#pragma unroll 8
        for (int e = 0; e < cnt; e++) {
            float pe = __shfl_sync(0xffffffffu, p_mine, srcLaneBase + e);
            int se = __shfl_sync(0xffffffffu, s_mine, srcLaneBase + e);
            den += pe;
            uint4 u = *reinterpret_cast<const uint4*>(&hbuf[(size_t)se * 256 + lt * 8]);
#pragma unroll
            for (int q = 0; q < 4; q++) {
                float2 f = __half22float2(*reinterpret_cast<const __half2*>(&(&u.x)[q]));
                acc[2 * q + 0] = fmaf(f.x, pe, acc[2 * q + 0]);
                acc[2 * q + 1] = fmaf(f.y, pe, acc[2 * q + 1]);
            }
        }
    }

    float inv = 1.f / (den + 1e-16f);
#pragma unroll
    for (int q = 0; q < 8; q++) acc[q] *= inv;

    if (!MEAN) {
        float4 b0 = *reinterpret_cast<const float4*>(&bias[lt * 8]);
        float4 b1 = *reinterpret_cast<const float4*>(&bias[lt * 8 + 4]);
        float4 o0 = make_float4(acc[0] + b0.x, acc[1] + b0.y, acc[2] + b0.z, acc[3] + b0.w);
        float4 o1 = make_float4(acc[4] + b1.x, acc[5] + b1.y, acc[6] + b1.z, acc[7] + b1.w);
        *reinterpret_cast<float4*>(&out[(size_t)node * 256 + lt * 8]) = o0;
        *reinterpret_cast<float4*>(&out[(size_t)node * 256 + lt * 8 + 4]) = o1;
    } else {
#pragma unroll
        for (int q = 0; q < 8; q++) sm[grp][lt * 8 + q] = acc[q];
        __syncwarp();
        if (lt < 8) {
            float* row = sm[grp];
            int c = lt * 8;
            float4 o0, o1;
            o0.x = (row[c + 0] + row[c + 64] + row[c + 128] + row[c + 192]) * 0.25f + bias[c + 0];
            o0.y = (row[c + 1] + row[c + 65] + row[c + 129] + row[c + 193]) * 0.25f + bias[c + 1];
            o0.z = (row[c + 2] + row[c + 66] + row[c + 130] + row[c + 194]) * 0.25f + bias[c + 2];
            o0.w = (row[c + 3] + row[c + 67] + row[c + 131] + row[c + 195]) * 0.25f + bias[c + 3];
            o1.x = (row[c + 4] + row[c + 68] + row[c + 132] + row[c + 196]) * 0.25f + bias[c + 4];
            o1.y = (row[c + 5] + row[c + 69] + row[c + 133] + row[c + 197]) * 0.25f + bias[c + 5];
            o1.z = (row[c + 6] + row[c + 70] + row[c + 134] + row[c + 198]) * 0.25f + bias[c + 6];
            o1.w = (row[c + 7] + row[c + 71] + row[c + 135] + row[c + 199]) * 0.25f + bias[c + 7];
            *reinterpret_cast<float4*>(&out[(size_t)node * 64 + c]) = o0;
            *reinterpret_cast<float4*>(&out[(size_t)node * 64 + c + 4]) = o1;
        }
    }
}

// ---------------- batchnorm stats ----------------
__global__ void k_bnstats(const float* __restrict__ x, float* __restrict__ stats,
                          int n, int C, int rowsPerBlk) {
    int c = threadIdx.x % C;
    int rl = threadIdx.x / C;
    int lanes = blockDim.x / C;
    int r0 = blockIdx.x * rowsPerBlk;
    int r1 = r0 + rowsPerBlk; if (r1 > n) r1 = n;
    float s = 0.f, s2 = 0.f;
    for (int r = r0 + rl; r < r1; r += lanes) {
        float v = x[(size_t)r * C + c];
        s += v; s2 += v * v;
    }
    __shared__ float sh[2][256];
    sh[0][threadIdx.x] = s; sh[1][threadIdx.x] = s2;
    __syncthreads();
    if (rl == 0) {
        for (int l = 1; l < lanes; l++) {
            s += sh[0][c + l * C]; s2 += sh[1][c + l * C];
        }
        atomicAdd(&stats[c], s);
        atomicAdd(&stats[C + c], s2);
    }
}

__global__ void k_bnprep(const float* __restrict__ stats, const float* __restrict__ g,
                         const float* __restrict__ b, float* __restrict__ scale,
                         float* __restrict__ shift, int n, int C) {
    int c = threadIdx.x + blockIdx.x * blockDim.x;
    if (c >= C) return;
    float invn = 1.f / (float)n;
    float mu = stats[c] * invn;
    float var = stats[C + c] * invn - mu * mu;
    float sc = rsqrtf(var + BN_EPS) * g[c];
    scale[c] = sc;
    shift[c] = b[c] - mu * sc;
}

// ---------------- fused bn4 + relu + final dot + sigmoid ----------------
__global__ void k_bnfin(const float* __restrict__ x, const float* __restrict__ stats,
                        const float* __restrict__ g, const float* __restrict__ b,
                        const float* __restrict__ w, const float* __restrict__ fb,
                        float* __restrict__ out) {
    int row = blockIdx.x * 8 + (threadIdx.x >> 5);
    int lane = threadIdx.x & 31;
    if (row >= NN) return;
    float invn = 1.f / (float)NN;
    float s = 0.f;
#pragma unroll
    for (int half = 0; half < 2; half++) {
        int c = lane + half * 32;
        float mu = stats[c] * invn;
        float var = stats[64 + c] * invn - mu * mu;
        float v = (x[(size_t)row * 64 + c] - mu) * rsqrtf(var + BN_EPS) * g[c] + b[c];
        v = fmaxf(v, 0.f);
        s = fmaf(v, w[c], s);
    }
#pragma unroll
    for (int o = 16; o; o >>= 1) s += __shfl_xor_sync(0xffffffffu, s, o);
    if (lane == 0) out[row] = 1.f / (1.f + __expf(-(s + fb[0])));
}

// ---------------- host launch ----------------
extern "C" void kernel_launch(void* const* d_in, const int* in_sizes, int n_in,
                              void* d_out, int out_size) {
    const float* x        = (const float*)d_in[0];
    const int*   ei       = (const int*)d_in[1];
    const float* W1       = (const float*)d_in[2];
    const float* a1_src   = (const float*)d_in[3];
    const float* a1_dst   = (const float*)d_in[4];
    const float* b1       = (const float*)d_in[5];
    const float* W2       = (const float*)d_in[6];
    const float* a2_src   = (const float*)d_in[7];
    const float* a2_dst   = (const float*)d_in[8];
    const float* b2       = (const float*)d_in[9];
    const float* bn1_g    = (const float*)d_in[10];
    const float* bn1_b    = (const float*)d_in[11];
    const float* bn2_g    = (const float*)d_in[12];
    const float* bn2_b    = (const float*)d_in[13];
    const float* bn3_g    = (const float*)d_in[14];
    const float* bn3_b    = (const float*)d_in[15];
    const float* bn4_g    = (const float*)d_in[16];
    const float* bn4_b    = (const float*)d_in[17];
    const float* lin1_W   = (const float*)d_in[18];
    const float* lin1_b   = (const float*)d_in[19];
    const float* lin2_W   = (const float*)d_in[20];
    const float* lin2_b   = (const float*)d_in[21];
    const float* fin_W    = (const float*)d_in[22];
    const float* fin_b    = (const float*)d_in[23];
    float* out            = (float*)d_out;

    float *p_agg, *p_s1, *p_s2, *p_als, *p_ald, *p_stats;
    float *p_scale, *p_shift;
    int *p_cnt, *p_rs, *p_cur, *p_srcs;
    __half *p_h;
    __nv_bfloat16 *p_ahi, *p_alo, *p_wthi, *p_wtlo, *p_wthi2, *p_wtlo2;
    cudaGetSymbolAddress((void**)&p_h, g_h);
    cudaGetSymbolAddress((void**)&p_agg, g_agg);
    cudaGetSymbolAddress((void**)&p_s1, g_s1);
    cudaGetSymbolAddress((void**)&p_s2, g_s2);
    cudaGetSymbolAddress((void**)&p_als, g_als);
    cudaGetSymbolAddress((void**)&p_ald, g_ald);
    cudaGetSymbolAddress((void**)&p_stats, g_stats);
    cudaGetSymbolAddress((void**)&p_scale, g_scale);
    cudaGetSymbolAddress((void**)&p_shift, g_shift);
    cudaGetSymbolAddress((void**)&p_cnt, g_cnt);
    cudaGetSymbolAddress((void**)&p_rs, g_rs);
    cudaGetSymbolAddress((void**)&p_cur, g_cur);
    cudaGetSymbolAddress((void**)&p_srcs, g_srcs);
    cudaGetSymbolAddress((void**)&p_ahi, g_ahi);
    cudaGetSymbolAddress((void**)&p_alo, g_alo);
    cudaGetSymbolAddress((void**)&p_wthi, g_wthi);
    cudaGetSymbolAddress((void**)&p_wtlo, g_wtlo);
    cudaGetSymbolAddress((void**)&p_wthi2, g_wthi2);
    cudaGetSymbolAddress((void**)&p_wtlo2, g_wtlo2);

    cudaFuncSetAttribute(k_wgemm, cudaFuncAttributeMaxDynamicSharedMemorySize, WG_SMEM);

    static cudaStream_t s2s = nullptr;
    static cudaEvent_t evFork = nullptr, evJoin = nullptr;
    if (!s2s) {
        cudaStreamCreateWithFlags(&s2s, cudaStreamNonBlocking);
        cudaEventCreateWithFlags(&evFork, cudaEventDisableTiming);
        cudaEventCreateWithFlags(&evJoin, cudaEventDisableTiming);
    }

    const int TB = 256;
    dim3 wg_grid(2, (NN + 127) / 128);
    dim3 gemm_grid_64(1, (NN + 63) / 64);
    int agg_blocks = NN / 8;

    float* st0 = p_stats;
    float* st1 = p_stats + 512;
    float* st2 = p_stats + 1024;
    float* st3 = p_stats + 1536;

    // ---- fork: side chain (CSR build + stats zero + W2 transpose) ----
    cudaEventRecord(evFork, 0);
    cudaStreamWaitEvent(s2s, evFork, 0);
    k_zeroi<<<(NN + TB - 1) / TB, TB, 0, s2s>>>(p_cnt, NN);
    k_count<<<(EE + TB - 1) / TB, TB, 0, s2s>>>(ei, p_cnt);
    k_scan<<<1, 1024, 0, s2s>>>(p_cnt, p_rs, p_cur);
    k_scatter<<<(EE + TB - 1) / TB, TB, 0, s2s>>>(ei, p_cur, p_srcs);
    k_zerof<<<8, TB, 0, s2s>>>(p_stats, 2048);
    k_cvt_wt<<<(256 * 256 + TB - 1) / TB, TB, 0, s2s>>>(W2, p_wthi2, p_wtlo2, 256, 256);
    cudaEventRecord(evJoin, s2s);

    // ---- main chain: conv1 GEMM ----
    k_cvt<<<(NN * 128 + TB - 1) / TB, TB>>>(x, p_ahi, p_alo, NN * 128);
    k_cvt_wt<<<(128 * 256 + TB - 1) / TB, TB>>>(W1, p_wthi, p_wtlo, 128, 256);
    k_wgemm<<<wg_grid, TB, WG_SMEM>>>(p_ahi, p_alo, p_wthi, p_wtlo, p_h,
                                      a1_src, a1_dst, p_als, p_ald,
                                      NN, 128, 256);

    // ---- join, then conv1 fused softmax+aggregation ----
    cudaStreamWaitEvent(0, evJoin, 0);
    k_agg8f<false><<<agg_blocks, TB>>>(p_h, p_als, p_ald, p_rs, p_srcs, b1, p_agg);

    // ---- bn1 stats -> scale/shift (applied in conv2 A conversion) ----
    k_bnstats<<<(NN + 255) / 256, TB>>>(p_agg, st0, NN, 256, 256);
    k_bnprep<<<1, 256>>>(st0, bn1_g, bn1_b, p_scale, p_shift, NN, 256);

    // ---- conv2 ----
    k_cvt_bn<<<(NN * 256 + TB - 1) / TB, TB>>>(p_agg, p_scale, p_shift,
                                               p_ahi, p_alo, NN * 256);
    k_wgemm<<<wg_grid, TB, WG_SMEM>>>(p_ahi, p_alo, p_wthi2, p_wtlo2, p_h,
                                      a2_src, a2_dst, p_als, p_ald,
                                      NN, 256, 256);
    k_agg8f<true><<<agg_blocks, TB>>>(p_h, p_als, p_ald, p_rs, p_srcs, b2, p_s1);

    // ---- bn2 stats -> folded into lin1 (no relu) ----
    k_bnstats<<<(NN + 255) / 256, TB>>>(p_s1, st1, NN, 64, 256);
    k_gemm<<<gemm_grid_64, TB>>>(p_s1, lin1_W, lin1_b, p_s2, NN, 64, 64,
                                 st1, bn2_g, bn2_b, 0);

    // ---- bn3 stats -> folded into lin2 (relu) ----
    k_bnstats<<<(NN + 255) / 256, TB>>>(p_s2, st2, NN, 64, 256);
    k_gemm<<<gemm_grid_64, TB>>>(p_s2, lin2_W, lin2_b, p_s1, NN, 64, 64,
                                 st2, bn3_g, bn3_b, 1);

    // ---- bn4 stats -> fused bn4+relu+fin dot+sigmoid ----
    k_bnstats<<<(NN + 255) / 256, TB>>>(p_s1, st3, NN, 64, 256);
    k_bnfin<<<(NN + 7) / 8, TB>>>(p_s1, st3, bn4_g, bn4_b, fin_W, fin_b, out);
}

// round 17
// speedup vs baseline: 1.2638x; 1.0600x over previous
#include <cuda_runtime.h>
#include <cuda_bf16.h>
#include <cuda_fp16.h>
#include <mma.h>
#include <math.h>
#include <stdint.h>

using namespace nvcuda;

#define NN 50000
#define EE 800000
#define BN_EPS 1e-5f

// ---------------- scratch (static device globals; no runtime alloc) ----------------
__device__ __half g_h[NN * 256];     // conv GEMM output, fp16
__device__ __half g_aggh[NN * 256];  // conv1 aggregate, fp16
__device__ float g_s1[NN * 64];
__device__ float g_s2[NN * 64];
__device__ float g_als[NN * 4];
__device__ float g_ald[NN * 4];
__device__ int   g_cnt[NN];
__device__ int   g_rs[NN + 1];
__device__ int   g_cur[NN];
__device__ int   g_srcs[EE];
__device__ float g_stats[2048];
__device__ float g_scale[256];
__device__ float g_shift[256];
__device__ __nv_bfloat16 g_ahi[NN * 256];
__device__ __nv_bfloat16 g_alo[NN * 256];
__device__ __nv_bfloat16 g_wthi[256 * 256];
__device__ __nv_bfloat16 g_wtlo[256 * 256];
__device__ __nv_bfloat16 g_wthi2[256 * 256];
__device__ __nv_bfloat16 g_wtlo2[256 * 256];

// ---------------- tiny utility kernels ----------------
__global__ void k_zeroi(int* __restrict__ p, int n) {
    int i = blockIdx.x * blockDim.x + threadIdx.x;
    if (i < n) p[i] = 0;
}
__global__ void k_zerof(float* __restrict__ p, int n) {
    int i = blockIdx.x * blockDim.x + threadIdx.x;
    if (i < n) p[i] = 0.f;
}

// ---------------- fp32 -> bf16 hi/lo split conversions ----------------
__global__ void k_cvt(const float* __restrict__ a, __nv_bfloat16* __restrict__ hi,
                      __nv_bfloat16* __restrict__ lo, int total) {
    int i = blockIdx.x * blockDim.x + threadIdx.x;
    if (i >= total) return;
    float v = a[i];
    __nv_bfloat16 h = __float2bfloat16(v);
    hi[i] = h;
    lo[i] = __float2bfloat16(v - __bfloat162float(h));
}

// conv2 A: relu(aggh*scale+shift) then split; aggh is fp16
__global__ void k_cvt_bn(const __half* __restrict__ a, const float* __restrict__ sc,
                         const float* __restrict__ sh, __nv_bfloat16* __restrict__ hi,
                         __nv_bfloat16* __restrict__ lo, int total) {
    int i = blockIdx.x * blockDim.x + threadIdx.x;
    if (i >= total) return;
    int c = i & 255;
    float v = fmaxf(fmaf(__half2float(a[i]), sc[c], sh[c]), 0.f);
    __nv_bfloat16 h = __float2bfloat16(v);
    hi[i] = h;
    lo[i] = __float2bfloat16(v - __bfloat162float(h));
}

// W [K,cout] -> transposed Wt [cout,K] hi/lo bf16
__global__ void k_cvt_wt(const float* __restrict__ w, __nv_bfloat16* __restrict__ hi,
                         __nv_bfloat16* __restrict__ lo, int K, int cout) {
    int i = blockIdx.x * blockDim.x + threadIdx.x;
    if (i >= K * cout) return;
    int k = i / cout;
    int c = i - k * cout;
    float v = w[i];
    __nv_bfloat16 h = __float2bfloat16(v);
    hi[c * K + k] = h;
    lo[c * K + k] = __float2bfloat16(v - __bfloat162float(h));
}

// ---------------- CSR build ----------------
__global__ void k_count(const int* __restrict__ ei, int* __restrict__ cnt) {
    int e = blockIdx.x * blockDim.x + threadIdx.x;
    if (e < EE) atomicAdd(&cnt[ei[EE + e]], 1);
}

__global__ void k_scan(const int* __restrict__ cnt, int* __restrict__ rs,
                       int* __restrict__ cur) {
    __shared__ int sh[1024];
    int t = threadIdx.x;
    const int n = NN;
    int chunk = (n + 1023) >> 10;
    int b0 = t * chunk;
    int b1 = b0 + chunk; if (b1 > n) b1 = n; if (b0 > n) b0 = n;
    int local = 0;
    for (int i = b0; i < b1; i++) local += cnt[i];
    sh[t] = local;
    __syncthreads();
    for (int off = 1; off < 1024; off <<= 1) {
        int v = (t >= off) ? sh[t - off] : 0;
        __syncthreads();
        sh[t] += v;
        __syncthreads();
    }
    int base = sh[t] - local;
    for (int i = b0; i < b1; i++) { rs[i] = base; cur[i] = base; base += cnt[i]; }
    if (t == 1023) rs[n] = sh[1023];
}

__global__ void k_scatter(const int* __restrict__ ei, int* __restrict__ cur,
                          int* __restrict__ srcs) {
    int e = blockIdx.x * blockDim.x + threadIdx.x;
    if (e < EE) {
        int d = ei[EE + e];
        int pos = atomicAdd(&cur[d], 1);
        srcs[pos] = ei[e];
    }
}

// ================= WMMA bf16-split GEMM, cp.async double-buffered =================
#define WG_LD        40
#define WG_MAT       (128 * WG_LD)
#define WG_BUF       (4 * WG_MAT)
#define WG_BUF_BYTES (WG_BUF * 2)
#define WG_SMEM      (2 * WG_BUF_BYTES)

__device__ __forceinline__ void cp16(uint32_t dst, const void* src, int sz) {
    asm volatile("cp.async.ca.shared.global [%0], [%1], 16, %2;"
                 :: "r"(dst), "l"(src), "r"(sz));
}
__device__ __forceinline__ void cp_commit() {
    asm volatile("cp.async.commit_group;" ::: "memory");
}
template <int N>
__device__ __forceinline__ void cp_wait() {
    asm volatile("cp.async.wait_group %0;" :: "n"(N) : "memory");
}

__device__ __forceinline__ uint32_t h2_bits(__half2 h) {
    return *reinterpret_cast<const uint32_t*>(&h);
}

__global__ void __launch_bounds__(256, 2)
k_wgemm(const __nv_bfloat16* __restrict__ Ahi, const __nv_bfloat16* __restrict__ Alo,
        const __nv_bfloat16* __restrict__ Bhi, const __nv_bfloat16* __restrict__ Blo,
        __half* __restrict__ C, const float* __restrict__ asrc,
        const float* __restrict__ adst, float* __restrict__ als,
        float* __restrict__ ald, int n, int K, int cout) {
    extern __shared__ __align__(16) __nv_bfloat16 sm[];
    int tid = threadIdx.x;
    int wid = tid >> 5;
    int lane = tid & 31;
    int wm = wid >> 1;
    int wn = wid & 1;
    int row0 = blockIdx.y * 128;
    int col0 = blockIdx.x * 128;

    int r0i = tid >> 2,         c0i = (tid & 3) * 8;
    int r1i = (tid + 256) >> 2, c1i = (tid & 3) * 8;
    int gr0 = row0 + r0i, gr1 = row0 + r1i;
    int sza0 = (gr0 < n) ? 16 : 0;
    int sza1 = (gr1 < n) ? 16 : 0;
    int ar0 = (gr0 < n) ? gr0 : 0;
    int ar1 = (gr1 < n) ? gr1 : 0;

    uint32_t sbase = (uint32_t)__cvta_generic_to_shared(sm);
    uint32_t so0 = (uint32_t)((r0i * WG_LD + c0i) * 2);
    uint32_t so1 = (uint32_t)((r1i * WG_LD + c1i) * 2);
    const uint32_t MATB = WG_MAT * 2;

    int nch = K >> 5;

    auto issue = [&](int ch, int buf) {
        int k0 = ch << 5;
        uint32_t b = sbase + (uint32_t)buf * WG_BUF_BYTES;
        size_t a0 = (size_t)ar0 * K + k0 + c0i;
        size_t a1 = (size_t)ar1 * K + k0 + c1i;
        size_t b0 = (size_t)(col0 + r0i) * K + k0 + c0i;
        size_t b1 = (size_t)(col0 + r1i) * K + k0 + c1i;
        cp16(b + so0, &Ahi[a0], sza0);
        cp16(b + so1, &Ahi[a1], sza1);
        cp16(b + MATB + so0, &Alo[a0], sza0);
        cp16(b + MATB + so1, &Alo[a1], sza1);
        cp16(b + 2 * MATB + so0, &Bhi[b0], 16);
        cp16(b + 2 * MATB + so1, &Bhi[b1], 16);
        cp16(b + 3 * MATB + so0, &Blo[b0], 16);
        cp16(b + 3 * MATB + so1, &Blo[b1], 16);
    };

    issue(0, 0);
    cp_commit();

    wmma::fragment<wmma::accumulator, 16, 16, 16, float> acc[2][4];
#pragma unroll
    for (int i = 0; i < 2; i++)
#pragma unroll
        for (int j = 0; j < 4; j++) wmma::fill_fragment(acc[i][j], 0.f);

    for (int ch = 0; ch < nch; ch++) {
        if (ch + 1 < nch) {
            issue(ch + 1, (ch + 1) & 1);
            cp_commit();
            cp_wait<1>();
        } else {
            cp_wait<0>();
        }
        __syncthreads();
        int cur = (ch & 1) * WG_BUF;
#pragma unroll
        for (int ks = 0; ks < 2; ks++) {
            wmma::fragment<wmma::matrix_a, 16, 16, 16, __nv_bfloat16, wmma::row_major> ah[2], al[2];
            const __nv_bfloat16* pa = &sm[cur + (wm * 32) * WG_LD + ks * 16];
            wmma::load_matrix_sync(ah[0], pa, WG_LD);
            wmma::load_matrix_sync(ah[1], pa + 16 * WG_LD, WG_LD);
            wmma::load_matrix_sync(al[0], pa + WG_MAT, WG_LD);
            wmma::load_matrix_sync(al[1], pa + WG_MAT + 16 * WG_LD, WG_LD);
#pragma unroll
            for (int j = 0; j < 4; j++) {
                wmma::fragment<wmma::matrix_b, 16, 16, 16, __nv_bfloat16, wmma::col_major> bh, bl;
                const __nv_bfloat16* pb =
                    &sm[cur + 2 * WG_MAT + (wn * 64 + j * 16) * WG_LD + ks * 16];
                wmma::load_matrix_sync(bh, pb, WG_LD);
                wmma::load_matrix_sync(bl, pb + WG_MAT, WG_LD);
                wmma::mma_sync(acc[0][j], ah[0], bh, acc[0][j]);
                wmma::mma_sync(acc[0][j], ah[0], bl, acc[0][j]);
                wmma::mma_sync(acc[0][j], al[0], bh, acc[0][j]);
                wmma::mma_sync(acc[1][j], ah[1], bh, acc[1][j]);
                wmma::mma_sync(acc[1][j], ah[1], bl, acc[1][j]);
                wmma::mma_sync(acc[1][j], al[1], bh, acc[1][j]);
            }
        }
        __syncthreads();
    }

    // ---- epilogue: stage C tile in smem, write C (fp16) coalesced, compute als/ald
    float* smC = reinterpret_cast<float*>(sm);
    const int CLD = 132;
#pragma unroll
    for (int i = 0; i < 2; i++)
#pragma unroll
        for (int j = 0; j < 4; j++)
            wmma::store_matrix_sync(smC + (wm * 32 + i * 16) * CLD + wn * 64 + j * 16,
                                    acc[i][j], CLD, wmma::mem_row_major);
    __syncthreads();

    for (int t = tid; t < 128 * 16; t += 256) {
        int r = t >> 4, c8 = (t & 15) * 8;
        int gr = row0 + r;
        if (gr < n) {
            const float* p = &smC[r * CLD + c8];
            uint4 u;
            u.x = h2_bits(__floats2half2_rn(p[0], p[1]));
            u.y = h2_bits(__floats2half2_rn(p[2], p[3]));
            u.z = h2_bits(__floats2half2_rn(p[4], p[5]));
            u.w = h2_bits(__floats2half2_rn(p[6], p[7]));
            *reinterpret_cast<uint4*>(&C[(size_t)gr * cout + col0 + c8]) = u;
        }
    }

    int half = lane >> 4;
    int l16 = lane & 15;
    int head = blockIdx.x * 2 + half;
    float4 as4 = *reinterpret_cast<const float4*>(&asrc[head * 64 + l16 * 4]);
    float4 ad4 = *reinterpret_cast<const float4*>(&adst[head * 64 + l16 * 4]);
#pragma unroll
    for (int rr = 0; rr < 16; rr++) {
        int r = wid * 16 + rr;
        int gr = row0 + r;
        float4 v = *reinterpret_cast<const float4*>(&smC[r * CLD + half * 64 + l16 * 4]);
        float vs = v.x * as4.x + v.y * as4.y + v.z * as4.z + v.w * as4.w;
        float vd = v.x * ad4.x + v.y * ad4.y + v.z * ad4.z + v.w * ad4.w;
#pragma unroll
        for (int o = 8; o; o >>= 1) {
            vs += __shfl_xor_sync(0xffffffffu, vs, o);
            vd += __shfl_xor_sync(0xffffffffu, vd, o);
        }
        if (l16 == 0 && gr < n) {
            als[gr * 4 + head] = vs;
            ald[gr * 4 + head] = vd;
        }
    }
}

// ---------------- small GEMM (64-wide), fused bn prep (from stats) + relu on A ----
__global__ void k_gemm(const float* __restrict__ A, const float* __restrict__ W,
                       const float* __restrict__ bias, float* __restrict__ C,
                       int n, int K, int cout,
                       const float* __restrict__ stats, const float* __restrict__ bng,
                       const float* __restrict__ bnb, int dorelu) {
    __shared__ __align__(16) float As[16][68];
    __shared__ __align__(16) float Ws[16][64];
    __shared__ float ssc[64], ssh[64];
    int tid = threadIdx.x;
    int tx = tid & 15;
    int ty = tid >> 4;
    int row0 = blockIdx.y * 64;
    int col0 = blockIdx.x * 64;

    if (stats && tid < 64) {
        float invn = 1.f / (float)n;
        float mu = stats[tid] * invn;
        float var = stats[64 + tid] * invn - mu * mu;
        float sc = rsqrtf(var + BN_EPS) * bng[tid];
        ssc[tid] = sc;
        ssh[tid] = bnb[tid] - mu * sc;
    }
    __syncthreads();

    float acc[4][4] = {};
    for (int k0 = 0; k0 < K; k0 += 16) {
#pragma unroll
        for (int i = 0; i < 4; i++) {
            int idx = tid + i * 256;
            int kk = idx & 15;
            int m  = idx >> 4;
            int gr = row0 + m;
            float v = (gr < n) ? A[(size_t)gr * K + k0 + kk] : 0.f;
            if (stats) {
                v = fmaf(v, ssc[k0 + kk], ssh[k0 + kk]);
                if (dorelu) v = fmaxf(v, 0.f);
            }
            As[kk][m] = v;
        }
#pragma unroll
        for (int i = 0; i < 4; i++) {
            int idx = tid + i * 256;
            int col = idx & 63;
            int kk  = idx >> 6;
            Ws[kk][col] = W[(size_t)(k0 + kk) * cout + col0 + col];
        }
        __syncthreads();
#pragma unroll
        for (int kk = 0; kk < 16; kk++) {
            float4 ra = *reinterpret_cast<const float4*>(&As[kk][ty * 4]);
            float4 rb = *reinterpret_cast<const float4*>(&Ws[kk][tx * 4]);
            float a[4] = {ra.x, ra.y, ra.z, ra.w};
            float b[4] = {rb.x, rb.y, rb.z, rb.w};
#pragma unroll
            for (int i = 0; i < 4; i++)
#pragma unroll
                for (int j = 0; j < 4; j++)
                    acc[i][j] = fmaf(a[i], b[j], acc[i][j]);
        }
        __syncthreads();
    }
#pragma unroll
    for (int i = 0; i < 4; i++) {
        int gr = row0 + ty * 4 + i;
        if (gr >= n) continue;
#pragma unroll
        for (int j = 0; j < 4; j++) {
            int gc = col0 + tx * 4 + j;
            float v = acc[i][j];
            if (bias) v += bias[gc];
            C[(size_t)gr * cout + gc] = v;
        }
    }
}

// ---- fused softmax + aggregation, 8 nodes/block, one warp/node, shfl p-share -----
// CONCAT variant: writes fp16 out + fused bn stats (sum/sumsq incl bias).
__global__ void k_agg8c(const __half* __restrict__ hbuf, const float* __restrict__ als,
                        const float* __restrict__ ald, const int* __restrict__ rs,
                        const int* __restrict__ srcs, const float* __restrict__ bias,
                        __half* __restrict__ out, float* __restrict__ stats) {
    int grp = threadIdx.x >> 5;
    int lt  = threadIdx.x & 31;
    int node = blockIdx.x * 8 + grp;
    __shared__ float sm[8][256];

    int h = lt >> 3;
    int el = lt & 7;
    int srcLaneBase = lt & 24;
    int beg = rs[node], end = rs[node + 1];
    float aldh = ald[node * 4 + h];

    float acc[8] = {};
    float den = 0.f;

    for (int j = beg; j < end; j += 8) {
        int je = j + el;
        float p_mine = 0.f;
        int s_mine = 0;
        if (je < end) {
            s_mine = srcs[je];
            float e = als[s_mine * 4 + h] + aldh;
            e = e > 0.f ? e : 0.2f * e;
            p_mine = __expf(e);
        }
        int cnt = end - j; if (cnt > 8) cnt = 8;
#pragma unroll 8
        for (int e = 0; e < cnt; e++) {
            float pe = __shfl_sync(0xffffffffu, p_mine, srcLaneBase + e);
            int se = __shfl_sync(0xffffffffu, s_mine, srcLaneBase + e);
            den += pe;
            uint4 u = *reinterpret_cast<const uint4*>(&hbuf[(size_t)se * 256 + lt * 8]);
#pragma unroll
            for (int q = 0; q < 4; q++) {
                float2 f = __half22float2(*reinterpret_cast<const __half2*>(&(&u.x)[q]));
                acc[2 * q + 0] = fmaf(f.x, pe, acc[2 * q + 0]);
                acc[2 * q + 1] = fmaf(f.y, pe, acc[2 * q + 1]);
            }
        }
    }

    float inv = 1.f / (den + 1e-16f);
    float4 b0 = *reinterpret_cast<const float4*>(&bias[lt * 8]);
    float4 b1 = *reinterpret_cast<const float4*>(&bias[lt * 8 + 4]);
    acc[0] = fmaf(acc[0], inv, b0.x); acc[1] = fmaf(acc[1], inv, b0.y);
    acc[2] = fmaf(acc[2], inv, b0.z); acc[3] = fmaf(acc[3], inv, b0.w);
    acc[4] = fmaf(acc[4], inv, b1.x); acc[5] = fmaf(acc[5], inv, b1.y);
    acc[6] = fmaf(acc[6], inv, b1.z); acc[7] = fmaf(acc[7], inv, b1.w);

    uint4 u;
    u.x = h2_bits(__floats2half2_rn(acc[0], acc[1]));
    u.y = h2_bits(__floats2half2_rn(acc[2], acc[3]));
    u.z = h2_bits(__floats2half2_rn(acc[4], acc[5]));
    u.w = h2_bits(__floats2half2_rn(acc[6], acc[7]));
    *reinterpret_cast<uint4*>(&out[(size_t)node * 256 + lt * 8]) = u;

    // fused bn1 stats: block-reduce 8 node rows, spread atomics
#pragma unroll
    for (int q = 0; q < 8; q++) sm[grp][lt * 8 + q] = acc[q];
    __syncthreads();
    int tid = threadIdx.x;
    float s = 0.f, s2 = 0.f;
#pragma unroll
    for (int g = 0; g < 8; g++) {
        float v = sm[g][tid];
        s += v;
        s2 = fmaf(v, v, s2);
    }
    atomicAdd(&stats[tid], s);
    atomicAdd(&stats[256 + tid], s2);
}

// MEAN variant: fp32 out [N,64], no stats fusion.
__global__ void k_agg8m(const __half* __restrict__ hbuf, const float* __restrict__ als,
                        const float* __restrict__ ald, const int* __restrict__ rs,
                        const int* __restrict__ srcs, const float* __restrict__ bias,
                        float* __restrict__ out) {
    int grp = threadIdx.x >> 5;
    int lt  = threadIdx.x & 31;
    int node = blockIdx.x * 8 + grp;
    __shared__ float sm[8][256];

    int h = lt >> 3;
    int el = lt & 7;
    int srcLaneBase = lt & 24;
    int beg = rs[node], end = rs[node + 1];
    float aldh = ald[node * 4 + h];

    float acc[8] = {};
    float den = 0.f;

    for (int j = beg; j < end; j += 8) {
        int je = j + el;
        float p_mine = 0.f;
        int s_mine = 0;
        if (je < end) {
            s_mine = srcs[je];
            float e = als[s_mine * 4 + h] + aldh;
            e = e > 0.f ? e : 0.2f * e;
            p_mine = __expf(e);
        }
        int cnt = end - j; if (cnt > 8) cnt = 8;
#pragma unroll 8
        for (int e = 0; e < cnt; e++) {
            float pe = __shfl_sync(0xffffffffu, p_mine, srcLaneBase + e);
            int se = __shfl_sync(0xffffffffu, s_mine, srcLaneBase + e);
            den += pe;
            uint4 u = *reinterpret_cast<const uint4*>(&hbuf[(size_t)se * 256 + lt * 8]);
#pragma unroll
            for (int q = 0; q < 4; q++) {
                float2 f = __half22float2(*reinterpret_cast<const __half2*>(&(&u.x)[q]));
                acc[2 * q + 0] = fmaf(f.x, pe, acc[2 * q + 0]);
                acc[2 * q + 1] = fmaf(f.y, pe, acc[2 * q + 1]);
            }
        }
    }

    float inv = 1.f / (den + 1e-16f);
#pragma unroll
    for (int q = 0; q < 8; q++) acc[q] *= inv;

#pragma unroll
    for (int q = 0; q < 8; q++) sm[grp][lt * 8 + q] = acc[q];
    __syncwarp();
    if (lt < 8) {
        float* row = sm[grp];
        int c = lt * 8;
        float4 o0, o1;
        o0.x = (row[c + 0] + row[c + 64] + row[c + 128] + row[c + 192]) * 0.25f + bias[c + 0];
        o0.y = (row[c + 1] + row[c + 65] + row[c + 129] + row[c + 193]) * 0.25f + bias[c + 1];
        o0.z = (row[c + 2] + row[c + 66] + row[c + 130] + row[c + 194]) * 0.25f + bias[c + 2];
        o0.w = (row[c + 3] + row[c + 67] + row[c + 131] + row[c + 195]) * 0.25f + bias[c + 3];
        o1.x = (row[c + 4] + row[c + 68] + row[c + 132] + row[c + 196]) * 0.25f + bias[c + 4];
        o1.y = (row[c + 5] + row[c + 69] + row[c + 133] + row[c + 197]) * 0.25f + bias[c + 5];
        o1.z = (row[c + 6] + row[c + 70] + row[c + 134] + row[c + 198]) * 0.25f + bias[c + 6];
        o1.w = (row[c + 7] + row[c + 71] + row[c + 135] + row[c + 199]) * 0.25f + bias[c + 7];
        *reinterpret_cast<float4*>(&out[(size_t)node * 64 + c]) = o0;
        *reinterpret_cast<float4*>(&out[(size_t)node * 64 + c + 4]) = o1;
    }
}

// ---------------- batchnorm stats ----------------
__global__ void k_bnstats(const float* __restrict__ x, float* __restrict__ stats,
                          int n, int C, int rowsPerBlk) {
    int c = threadIdx.x % C;
    int rl = threadIdx.x / C;
    int lanes = blockDim.x / C;
    int r0 = blockIdx.x * rowsPerBlk;
    int r1 = r0 + rowsPerBlk; if (r1 > n) r1 = n;
    float s = 0.f, s2 = 0.f;
    for (int r = r0 + rl; r < r1; r += lanes) {
        float v = x[(size_t)r * C + c];
        s += v; s2 += v * v;
    }
    __shared__ float sh[2][256];
    sh[0][threadIdx.x] = s; sh[1][threadIdx.x] = s2;
    __syncthreads();
    if (rl == 0) {
        for (int l = 1; l < lanes; l++) {
            s += sh[0][c + l * C]; s2 += sh[1][c + l * C];
        }
        atomicAdd(&stats[c], s);
        atomicAdd(&stats[C + c], s2);
    }
}

__global__ void k_bnprep(const float* __restrict__ stats, const float* __restrict__ g,
                         const float* __restrict__ b, float* __restrict__ scale,
                         float* __restrict__ shift, int n, int C) {
    int c = threadIdx.x + blockIdx.x * blockDim.x;
    if (c >= C) return;
    float invn = 1.f / (float)n;
    float mu = stats[c] * invn;
    float var = stats[C + c] * invn - mu * mu;
    float sc = rsqrtf(var + BN_EPS) * g[c];
    scale[c] = sc;
    shift[c] = b[c] - mu * sc;
}

// ---------------- fused bn4 + relu + final dot + sigmoid ----------------
__global__ void k_bnfin(const float* __restrict__ x, const float* __restrict__ stats,
                        const float* __restrict__ g, const float* __restrict__ b,
                        const float* __restrict__ w, const float* __restrict__ fb,
                        float* __restrict__ out) {
    int row = blockIdx.x * 8 + (threadIdx.x >> 5);
    int lane = threadIdx.x & 31;
    if (row >= NN) return;
    float invn = 1.f / (float)NN;
    float s = 0.f;
#pragma unroll
    for (int half = 0; half < 2; half++) {
        int c = lane + half * 32;
        float mu = stats[c] * invn;
        float var = stats[64 + c] * invn - mu * mu;
        float v = (x[(size_t)row * 64 + c] - mu) * rsqrtf(var + BN_EPS) * g[c] + b[c];
        v = fmaxf(v, 0.f);
        s = fmaf(v, w[c], s);
    }
#pragma unroll
    for (int o = 16; o; o >>= 1) s += __shfl_xor_sync(0xffffffffu, s, o);
    if (lane == 0) out[row] = 1.f / (1.f + __expf(-(s + fb[0])));
}

// ---------------- host launch ----------------
extern "C" void kernel_launch(void* const* d_in, const int* in_sizes, int n_in,
                              void* d_out, int out_size) {
    const float* x        = (const float*)d_in[0];
    const int*   ei       = (const int*)d_in[1];
    const float* W1       = (const float*)d_in[2];
    const float* a1_src   = (const float*)d_in[3];
    const float* a1_dst   = (const float*)d_in[4];
    const float* b1       = (const float*)d_in[5];
    const float* W2       = (const float*)d_in[6];
    const float* a2_src   = (const float*)d_in[7];
    const float* a2_dst   = (const float*)d_in[8];
    const float* b2       = (const float*)d_in[9];
    const float* bn1_g    = (const float*)d_in[10];
    const float* bn1_b    = (const float*)d_in[11];
    const float* bn2_g    = (const float*)d_in[12];
    const float* bn2_b    = (const float*)d_in[13];
    const float* bn3_g    = (const float*)d_in[14];
    const float* bn3_b    = (const float*)d_in[15];
    const float* bn4_g    = (const float*)d_in[16];
    const float* bn4_b    = (const float*)d_in[17];
    const float* lin1_W   = (const float*)d_in[18];
    const float* lin1_b   = (const float*)d_in[19];
    const float* lin2_W   = (const float*)d_in[20];
    const float* lin2_b   = (const float*)d_in[21];
    const float* fin_W    = (const float*)d_in[22];
    const float* fin_b    = (const float*)d_in[23];
    float* out            = (float*)d_out;

    float *p_s1, *p_s2, *p_als, *p_ald, *p_stats, *p_scale, *p_shift;
    int *p_cnt, *p_rs, *p_cur, *p_srcs;
    __half *p_h, *p_aggh;
    __nv_bfloat16 *p_ahi, *p_alo, *p_wthi, *p_wtlo, *p_wthi2, *p_wtlo2;
    cudaGetSymbolAddress((void**)&p_h, g_h);
    cudaGetSymbolAddress((void**)&p_aggh, g_aggh);
    cudaGetSymbolAddress((void**)&p_s1, g_s1);
    cudaGetSymbolAddress((void**)&p_s2, g_s2);
    cudaGetSymbolAddress((void**)&p_als, g_als);
    cudaGetSymbolAddress((void**)&p_ald, g_ald);
    cudaGetSymbolAddress((void**)&p_stats, g_stats);
    cudaGetSymbolAddress((void**)&p_scale, g_scale);
    cudaGetSymbolAddress((void**)&p_shift, g_shift);
    cudaGetSymbolAddress((void**)&p_cnt, g_cnt);
    cudaGetSymbolAddress((void**)&p_rs, g_rs);
    cudaGetSymbolAddress((void**)&p_cur, g_cur);
    cudaGetSymbolAddress((void**)&p_srcs, g_srcs);
    cudaGetSymbolAddress((void**)&p_ahi, g_ahi);
    cudaGetSymbolAddress((void**)&p_alo, g_alo);
    cudaGetSymbolAddress((void**)&p_wthi, g_wthi);
    cudaGetSymbolAddress((void**)&p_wtlo, g_wtlo);
    cudaGetSymbolAddress((void**)&p_wthi2, g_wthi2);
    cudaGetSymbolAddress((void**)&p_wtlo2, g_wtlo2);

    cudaFuncSetAttribute(k_wgemm, cudaFuncAttributeMaxDynamicSharedMemorySize, WG_SMEM);

    static cudaStream_t s2s = nullptr;
    static cudaEvent_t evFork = nullptr, evJoin = nullptr;
    if (!s2s) {
        cudaStreamCreateWithFlags(&s2s, cudaStreamNonBlocking);
        cudaEventCreateWithFlags(&evFork, cudaEventDisableTiming);
        cudaEventCreateWithFlags(&evJoin, cudaEventDisableTiming);
    }

    const int TB = 256;
    dim3 wg_grid(2, (NN + 127) / 128);
    dim3 gemm_grid_64(1, (NN + 63) / 64);
    int agg_blocks = NN / 8;

    float* st0 = p_stats;            // bn1: [sum256][sumsq256]
    float* st1 = p_stats + 512;      // bn2
    float* st2 = p_stats + 1024;     // bn3
    float* st3 = p_stats + 1536;     // bn4

    // ---- fork: side chain (CSR build + stats zero + W2 transpose) ----
    cudaEventRecord(evFork, 0);
    cudaStreamWaitEvent(s2s, evFork, 0);
    k_zeroi<<<(NN + TB - 1) / TB, TB, 0, s2s>>>(p_cnt, NN);
    k_count<<<(EE + TB - 1) / TB, TB, 0, s2s>>>(ei, p_cnt);
    k_scan<<<1, 1024, 0, s2s>>>(p_cnt, p_rs, p_cur);
    k_scatter<<<(EE + TB - 1) / TB, TB, 0, s2s>>>(ei, p_cur, p_srcs);
    k_zerof<<<8, TB, 0, s2s>>>(p_stats, 2048);
    k_cvt_wt<<<(256 * 256 + TB - 1) / TB, TB, 0, s2s>>>(W2, p_wthi2, p_wtlo2, 256, 256);
    cudaEventRecord(evJoin, s2s);

    // ---- main chain: conv1 GEMM ----
    k_cvt<<<(NN * 128 + TB - 1) / TB, TB>>>(x, p_ahi, p_alo, NN * 128);
    k_cvt_wt<<<(128 * 256 + TB - 1) / TB, TB>>>(W1, p_wthi, p_wtlo, 128, 256);
    k_wgemm<<<wg_grid, TB, WG_SMEM>>>(p_ahi, p_alo, p_wthi, p_wtlo, p_h,
                                      a1_src, a1_dst, p_als, p_ald,
                                      NN, 128, 256);

    // ---- join, then conv1 fused softmax+aggregation (+bn1 stats) ----
    cudaStreamWaitEvent(0, evJoin, 0);
    k_agg8c<<<agg_blocks, TB>>>(p_h, p_als, p_ald, p_rs, p_srcs, b1, p_aggh, st0);

    // ---- bn1 scale/shift from fused stats ----
    k_bnprep<<<1, 256>>>(st0, bn1_g, bn1_b, p_scale, p_shift, NN, 256);

    // ---- conv2 ----
    k_cvt_bn<<<(NN * 256 + TB - 1) / TB, TB>>>(p_aggh, p_scale, p_shift,
                                               p_ahi, p_alo, NN * 256);
    k_wgemm<<<wg_grid, TB, WG_SMEM>>>(p_ahi, p_alo, p_wthi2, p_wtlo2, p_h,
                                      a2_src, a2_dst, p_als, p_ald,
                                      NN, 256, 256);
    k_agg8m<<<agg_blocks, TB>>>(p_h, p_als, p_ald, p_rs, p_srcs, b2, p_s1);

    // ---- bn2 stats -> folded into lin1 (no relu) ----
    k_bnstats<<<(NN + 255) / 256, TB>>>(p_s1, st1, NN, 64, 256);
    k_gemm<<<gemm_grid_64, TB>>>(p_s1, lin1_W, lin1_b, p_s2, NN, 64, 64,
                                 st1, bn2_g, bn2_b, 0);

    // ---- bn3 stats -> folded into lin2 (relu) ----
    k_bnstats<<<(NN + 255) / 256, TB>>>(p_s2, st2, NN, 64, 256);
    k_gemm<<<gemm_grid_64, TB>>>(p_s2, lin2_W, lin2_b, p_s1, NN, 64, 64,
                                 st2, bn3_g, bn3_b, 1);

    // ---- bn4 stats -> fused bn4+relu+fin dot+sigmoid ----
    k_bnstats<<<(NN + 255) / 256, TB>>>(p_s1, st3, NN, 64, 256);
    k_bnfin<<<(NN + 7) / 8, TB>>>(p_s1, st3, bn4_g, bn4_b, fin_W, fin_b, out);
}